// round 14
// baseline (speedup 1.0000x reference)
#include <cuda_runtime.h>
#include <cstdint>
#include <math.h>

// Problem constants
#define BB   4
#define SS   1024
#define DD   1024
#define HH   16
#define DH   64
#define DFF  4096
#define MM   (BB*SS)          // 4096 rows
#define LN_EPS 1e-5f

// -------------------- scratch (static device globals; no runtime alloc) ----
__device__ float g_q[MM*DD];
__device__ float g_k[MM*DD];
__device__ float g_v[MM*DD];
__device__ float g_k2[MM*DD];
__device__ float g_v2[MM*DD];
__device__ float g_ctx[MM*DD];
__device__ float g_mha[MM*DD];
__device__ float g_res1[MM*DD];
__device__ float g_res2[MM*DD];
__device__ float g_ffn[(size_t)MM*DFF];
__device__ float g_wt[16u*1024u*1024u];   // tf32-rounded weights (concatenated)
__device__ float g_xr[MM*DD];
__device__ float g_encr[MM*DD];
__device__ float g_res1r[MM*DD];
__device__ float g_res2r[MM*DD];

__device__ __forceinline__ uint32_t cvt_tf32(float f) {
    uint32_t r;
    asm("cvt.rna.tf32.f32 %0, %1;" : "=r"(r) : "f"(f));
    return r;
}
__device__ __forceinline__ float rnd_tf32(float f) {
    return __uint_as_float(cvt_tf32(f));
}
__device__ __forceinline__ uint32_t smem_u32(const void* p) {
    uint32_t a;
    asm("{ .reg .u64 t; cvta.to.shared.u64 t, %1; cvt.u32.u64 %0, t; }"
        : "=r"(a) : "l"(p));
    return a;
}
__device__ __forceinline__ void cp16(uint32_t dst, const void* src) {
    asm volatile("cp.async.ca.shared.global [%0], [%1], 16;" :: "r"(dst), "l"(src));
}
#define CP_COMMIT() asm volatile("cp.async.commit_group;")
#define CP_WAIT0()  asm volatile("cp.async.wait_group 0;")

__device__ __forceinline__ void mma_tf32(float* c,
    uint32_t a0, uint32_t a1, uint32_t a2, uint32_t a3,
    uint32_t b0, uint32_t b1)
{
    asm volatile(
        "mma.sync.aligned.m16n8k8.row.col.f32.tf32.tf32.f32 "
        "{%0,%1,%2,%3}, {%4,%5,%6,%7}, {%8,%9}, {%0,%1,%2,%3};"
        : "+f"(c[0]), "+f"(c[1]), "+f"(c[2]), "+f"(c[3])
        : "r"(a0), "r"(a1), "r"(a2), "r"(a3), "r"(b0), "r"(b1));
}

// ============================================================================
// Merged tf32 rounding: 12 tensors, one launch. Each block = 4096 floats.
// ============================================================================
struct R12 {
    const float4* src[12];
    float4* dst[12];
    int cum[13];
};

__global__ __launch_bounds__(256) void round_all(R12 r)
{
    const int bid = blockIdx.x;
    int ti = 0;
#pragma unroll
    for (int i = 0; i < 12; i++)
        if (bid >= r.cum[i + 1]) ti = i + 1;
    const float4* s = r.src[ti];
    float4* d = r.dst[ti];
    const int base = (bid - r.cum[ti]) * 1024 + threadIdx.x;
#pragma unroll
    for (int j = 0; j < 4; j++) {
        const int idx = base + j * 256;
        float4 v = s[idx];
        float4 o;
        o.x = rnd_tf32(v.x); o.y = rnd_tf32(v.y);
        o.z = rnd_tf32(v.z); o.w = rnd_tf32(v.w);
        d[idx] = o;
    }
}

// ============================================================================
// GEMM body: C = A@W + bias. CTA 128x128, BK=32, 128 threads = 4 warps (2x2),
// warp tile 64x64. 2-stage pipeline: wait0 -> sync -> issue-next -> compute.
// ============================================================================
#define AS_STR 36
#define BS_STR 136
#define A_FLTS (128*AS_STR)
#define B_FLTS (32*BS_STR)
#define BUF_FLTS (A_FLTS + B_FLTS)       // 8960
#define GEMM_SMEM_BYTES (2*BUF_FLTS*4)   // 71680

template<bool RELU>
__device__ __forceinline__ void gemm_body(
    const float* __restrict__ A, const float* __restrict__ W,
    const float* __restrict__ bias, float* __restrict__ C,
    int N, int K, bool round_out,
    float* sm, int row0, int col0)
{
    const uint32_t smb = smem_u32(sm);
    const int tid = threadIdx.x;              // 0..127
    const int wid = tid >> 5, lane = tid & 31;
    const int g = lane >> 2, t = lane & 3;
    const int wm = (wid >> 1) * 64;           // 2x2 warp grid, 64x64 tiles
    const int wn = (wid & 1) * 64;

    int a_row[8], a_c4[8], b_k[8], b_n4[8];
#pragma unroll
    for (int it = 0; it < 8; it++) {
        int lin = it * 128 + tid;
        a_row[it] = lin >> 3;
        a_c4[it]  = (lin & 7) * 4;
        b_k[it]   = lin >> 5;
        b_n4[it]  = (lin & 31) * 4;
    }

    float acc[4][8][4];
#pragma unroll
    for (int mt = 0; mt < 4; mt++)
#pragma unroll
        for (int nt = 0; nt < 8; nt++)
#pragma unroll
            for (int i = 0; i < 4; i++) acc[mt][nt][i] = 0.f;

    const int nchunk = K >> 5;

    {
        const uint32_t ab = smb, bb = smb + A_FLTS * 4;
#pragma unroll
        for (int it = 0; it < 8; it++) {
            cp16(ab + (a_row[it] * AS_STR + a_c4[it]) * 4,
                 A + (size_t)(row0 + a_row[it]) * K + a_c4[it]);
            cp16(bb + (b_k[it] * BS_STR + b_n4[it]) * 4,
                 W + (size_t)b_k[it] * N + col0 + b_n4[it]);
        }
        CP_COMMIT();
    }

    for (int ic = 0; ic < nchunk; ic++) {
        const int p = ic & 1;
        CP_WAIT0();
        __syncthreads();
        if (ic + 1 < nchunk) {
            const int k1 = (ic + 1) << 5;
            const uint32_t ab = smb + (p ? 0 : BUF_FLTS * 4);
            const uint32_t bb = ab + A_FLTS * 4;
#pragma unroll
            for (int it = 0; it < 8; it++) {
                cp16(ab + (a_row[it] * AS_STR + a_c4[it]) * 4,
                     A + (size_t)(row0 + a_row[it]) * K + k1 + a_c4[it]);
                cp16(bb + (b_k[it] * BS_STR + b_n4[it]) * 4,
                     W + (size_t)(k1 + b_k[it]) * N + col0 + b_n4[it]);
            }
            CP_COMMIT();
        }

        const float* sA = sm + (p ? BUF_FLTS : 0);
        const float* sB = sA + A_FLTS;
#pragma unroll
        for (int ks = 0; ks < 4; ks++) {
            const int k8 = ks * 8;
            uint32_t af[4][4];
#pragma unroll
            for (int mt = 0; mt < 4; mt++) {
                const int r = wm + mt * 16 + g;
                af[mt][0] = __float_as_uint(sA[r * AS_STR + k8 + t]);
                af[mt][1] = __float_as_uint(sA[(r + 8) * AS_STR + k8 + t]);
                af[mt][2] = __float_as_uint(sA[r * AS_STR + k8 + 4 + t]);
                af[mt][3] = __float_as_uint(sA[(r + 8) * AS_STR + k8 + 4 + t]);
            }
            uint32_t bf[8][2];
#pragma unroll
            for (int nt = 0; nt < 8; nt++) {
                const int n = wn + nt * 8 + g;
                bf[nt][0] = __float_as_uint(sB[(k8 + t) * BS_STR + n]);
                bf[nt][1] = __float_as_uint(sB[(k8 + 4 + t) * BS_STR + n]);
            }
#pragma unroll
            for (int mt = 0; mt < 4; mt++)
#pragma unroll
                for (int nt = 0; nt < 8; nt++)
                    mma_tf32(acc[mt][nt], af[mt][0], af[mt][1], af[mt][2], af[mt][3],
                             bf[nt][0], bf[nt][1]);
        }
    }

#pragma unroll
    for (int mt = 0; mt < 4; mt++) {
        const int ra = row0 + wm + mt * 16 + g;
#pragma unroll
        for (int nt = 0; nt < 8; nt++) {
            const int cc = col0 + wn + nt * 8 + 2 * t;
            float2 bv = *(const float2*)(bias + cc);
            float v0 = acc[mt][nt][0] + bv.x;
            float v1 = acc[mt][nt][1] + bv.y;
            float v2 = acc[mt][nt][2] + bv.x;
            float v3 = acc[mt][nt][3] + bv.y;
            if (RELU) {
                v0 = fmaxf(v0, 0.f); v1 = fmaxf(v1, 0.f);
                v2 = fmaxf(v2, 0.f); v3 = fmaxf(v3, 0.f);
            }
            if (round_out) {
                v0 = rnd_tf32(v0); v1 = rnd_tf32(v1);
                v2 = rnd_tf32(v2); v3 = rnd_tf32(v3);
            }
            *(float2*)(C + (size_t)ra * N + cc) = make_float2(v0, v1);
            *(float2*)(C + (size_t)(ra + 8) * N + cc) = make_float2(v2, v3);
        }
    }
}

template<bool RELU>
__global__ void __launch_bounds__(128, 2) gemm_ca(
    const float* __restrict__ A, const float* __restrict__ W,
    const float* __restrict__ bias, float* __restrict__ C,
    int N, int K, int round_out)
{
    extern __shared__ float sm[];
    gemm_body<RELU>(A, W, bias, C, N, K, round_out != 0,
                    sm, blockIdx.y * 128, blockIdx.x * 128);
}

// Batched projections: z selects (A, W, bias, C, round flag). Up to 3 slots.
struct QKV {
    const float* A[3];
    const float* W[3];
    const float* b[3];
    float* C[3];
    int round_flag[3];
};

__global__ void __launch_bounds__(128, 2) gemm_qkv(QKV q)
{
    extern __shared__ float sm[];
    const int z = blockIdx.z;
    gemm_body<false>(q.A[z], q.W[z], q.b[z], q.C[z], DD, DD,
                     q.round_flag[z] != 0, sm, blockIdx.y * 128, blockIdx.x * 128);
}

// ============================================================================
// Attention logits v4: CTA owns 128 rows x ALL 1024 cols of one (bh);
// loops over 8 column tiles. Q loaded once; K tiles double-buffered with the
// proven GEMM pipeline (wait0 -> sync -> issue K[x+1] -> compute K[x]).
// 128 threads = 4 warps of 64x64. SMEM 104.4KB -> 2 CTAs/SM.
// ============================================================================
#define L4_STR 68
#define L4_TILE (128*L4_STR)              // floats per tile
#define LOG_SMEM_BYTES (3*L4_TILE*4)      // 104448

__global__ void __launch_bounds__(128, 2) attn_logits4(
    const float* __restrict__ q, const float* __restrict__ k,
    const float* __restrict__ mask, float* __restrict__ out)
{
    extern __shared__ float sm[];
    float* Qs = sm;
    float* Kb[2] = { sm + L4_TILE, sm + 2 * L4_TILE };
    const uint32_t qs_u32 = smem_u32(Qs);
    const uint32_t kb_u32[2] = { smem_u32(Kb[0]), smem_u32(Kb[1]) };

    const int tid = threadIdx.x;              // 0..127
    const int wid = tid >> 5, lane = tid & 31;
    const int g = lane >> 2, t = lane & 3;
    const int wm = (wid >> 1) * 64;
    const int wn = (wid & 1) * 64;

    const int bh = blockIdx.y;
    const int b = bh >> 4, h = bh & 15;
    const int row0 = blockIdx.x * 128;
    const float* qb = q + (size_t)b * SS * DD + h * DH;
    const float* kb = k + (size_t)b * SS * DD + h * DH;
    const float* mb = mask + (size_t)b * SS * SS;
    float* ob = out + (size_t)bh * SS * SS;

    // per-thread load map: 16 iterations cover 128 rows x 64 k (2048 float4)
    int l_r[16], l_c4[16];
#pragma unroll
    for (int it = 0; it < 16; it++) {
        const int lin = it * 128 + tid;
        l_r[it]  = lin >> 4;
        l_c4[it] = (lin & 15) * 4;
    }

    // prologue: Q tile + K tile 0 in one group
#pragma unroll
    for (int it = 0; it < 16; it++) {
        cp16(qs_u32 + (l_r[it] * L4_STR + l_c4[it]) * 4,
             qb + (size_t)(row0 + l_r[it]) * DD + l_c4[it]);
        cp16(kb_u32[0] + (l_r[it] * L4_STR + l_c4[it]) * 4,
             kb + (size_t)l_r[it] * DD + l_c4[it]);
    }
    CP_COMMIT();

    for (int x = 0; x < 8; x++) {
        const int p = x & 1;
        CP_WAIT0();
        __syncthreads();
        if (x + 1 < 8) {
            const int col1 = (x + 1) * 128;
            const uint32_t kd = kb_u32[p ^ 1];
#pragma unroll
            for (int it = 0; it < 16; it++)
                cp16(kd + (l_r[it] * L4_STR + l_c4[it]) * 4,
                     kb + (size_t)(col1 + l_r[it]) * DD + l_c4[it]);
            CP_COMMIT();
        }

        const float* Ks = Kb[p];
        float acc[4][8][4];
#pragma unroll
        for (int mt = 0; mt < 4; mt++)
#pragma unroll
            for (int nt = 0; nt < 8; nt++)
#pragma unroll
                for (int i = 0; i < 4; i++) acc[mt][nt][i] = 0.f;

#pragma unroll
        for (int ks = 0; ks < 8; ks++) {
            const int k8 = ks * 8;
            uint32_t af[4][4];
#pragma unroll
            for (int mt = 0; mt < 4; mt++) {
                const int r = wm + mt * 16 + g;
                af[mt][0] = __float_as_uint(Qs[r * L4_STR + k8 + t]);
                af[mt][1] = __float_as_uint(Qs[(r + 8) * L4_STR + k8 + t]);
                af[mt][2] = __float_as_uint(Qs[r * L4_STR + k8 + 4 + t]);
                af[mt][3] = __float_as_uint(Qs[(r + 8) * L4_STR + k8 + 4 + t]);
            }
            uint32_t bf[8][2];
#pragma unroll
            for (int nt = 0; nt < 8; nt++) {
                const int n = wn + nt * 8 + g;
                bf[nt][0] = __float_as_uint(Ks[n * L4_STR + k8 + t]);
                bf[nt][1] = __float_as_uint(Ks[n * L4_STR + k8 + 4 + t]);
            }
#pragma unroll
            for (int mt = 0; mt < 4; mt++)
#pragma unroll
                for (int nt = 0; nt < 8; nt++)
                    mma_tf32(acc[mt][nt], af[mt][0], af[mt][1], af[mt][2], af[mt][3],
                             bf[nt][0], bf[nt][1]);
        }

        const int col0 = x * 128;
#pragma unroll
        for (int mt = 0; mt < 4; mt++) {
            const int r = row0 + wm + mt * 16 + g;
#pragma unroll
            for (int nt = 0; nt < 8; nt++) {
                const int c = col0 + wn + nt * 8 + 2 * t;
                float2 m0 = *(const float2*)(mb + (size_t)r * SS + c);
                float2 m1 = *(const float2*)(mb + (size_t)(r + 8) * SS + c);
                *(float2*)(ob + (size_t)r * SS + c) =
                    make_float2(acc[mt][nt][0] * 0.125f + m0.x,
                                acc[mt][nt][1] * 0.125f + m0.y);
                *(float2*)(ob + (size_t)(r + 8) * SS + c) =
                    make_float2(acc[mt][nt][2] * 0.125f + m1.x,
                                acc[mt][nt][3] * 0.125f + m1.y);
            }
        }
    }
}

// ============================================================================
// Batched AV v2: CTA 256x64, 128 threads = 4 warps of 64x64 (LDS/MMA = 1.0).
// 2-stage cp.async pipeline over 32 k-chunks.
// ============================================================================
#define AV2A_STR 36
#define AV2B_STR 72
#define AV2_A_FLTS (256*AV2A_STR)          // 9216
#define AV2_B_FLTS (32*AV2B_STR)           // 2304
#define AV2_BUF (AV2_A_FLTS + AV2_B_FLTS)  // 11520
#define AV_SMEM_BYTES (2*AV2_BUF*4)        // 92160

__global__ void __launch_bounds__(128, 2) attn_av2(
    const float* __restrict__ w, const float* __restrict__ v,
    float* __restrict__ ctx)
{
    extern __shared__ float sm[];
    const uint32_t smb = smem_u32(sm);
    const int tid = threadIdx.x;              // 0..127
    const int wid = tid >> 5, lane = tid & 31;
    const int g = lane >> 2, t = lane & 3;
    const int wm = wid * 64;                  // 4 warps stacked in M

    const int bh = blockIdx.y;
    const int b = bh >> 4, h = bh & 15;
    const int row0 = blockIdx.x * 256;
    const float* wb = w + (size_t)bh * SS * SS;
    const float* vb = v + (size_t)b * SS * DD + h * DH;

    int a_row[16], a_c4[16], b_k[4], b_n4[4];
#pragma unroll
    for (int it = 0; it < 16; it++) {
        int lin = it * 128 + tid;
        a_row[it] = lin >> 3;                 // 0..255
        a_c4[it]  = (lin & 7) * 4;            // 0..28
    }
#pragma unroll
    for (int it = 0; it < 4; it++) {
        int lin = it * 128 + tid;
        b_k[it]  = lin >> 4;                  // 0..31
        b_n4[it] = (lin & 15) * 4;            // 0..60
    }

    float acc[4][8][4];
#pragma unroll
    for (int mt = 0; mt < 4; mt++)
#pragma unroll
        for (int nt = 0; nt < 8; nt++)
#pragma unroll
            for (int i = 0; i < 4; i++) acc[mt][nt][i] = 0.f;

    {
        const uint32_t ab = smb, bb = smb + AV2_A_FLTS * 4;
#pragma unroll
        for (int it = 0; it < 16; it++)
            cp16(ab + (a_row[it] * AV2A_STR + a_c4[it]) * 4,
                 wb + (size_t)(row0 + a_row[it]) * SS + a_c4[it]);
#pragma unroll
        for (int it = 0; it < 4; it++)
            cp16(bb + (b_k[it] * AV2B_STR + b_n4[it]) * 4,
                 vb + (size_t)b_k[it] * DD + b_n4[it]);
        CP_COMMIT();
    }

    for (int ic = 0; ic < 32; ic++) {
        const int p = ic & 1;
        CP_WAIT0();
        __syncthreads();
        if (ic + 1 < 32) {
            const int k1 = (ic + 1) << 5;
            const uint32_t ab = smb + (p ? 0 : AV2_BUF * 4);
            const uint32_t bb = ab + AV2_A_FLTS * 4;
#pragma unroll
            for (int it = 0; it < 16; it++)
                cp16(ab + (a_row[it] * AV2A_STR + a_c4[it]) * 4,
                     wb + (size_t)(row0 + a_row[it]) * SS + k1 + a_c4[it]);
#pragma unroll
            for (int it = 0; it < 4; it++)
                cp16(bb + (b_k[it] * AV2B_STR + b_n4[it]) * 4,
                     vb + (size_t)(k1 + b_k[it]) * DD + b_n4[it]);
            CP_COMMIT();
        }

        const float* sA = sm + (p ? AV2_BUF : 0);
        const float* sB = sA + AV2_A_FLTS;
#pragma unroll
        for (int ks = 0; ks < 4; ks++) {
            const int k8 = ks * 8;
            uint32_t af[4][4];
#pragma unroll
            for (int mt = 0; mt < 4; mt++) {
                const int r = wm + mt * 16 + g;
                af[mt][0] = __float_as_uint(sA[r * AV2A_STR + k8 + t]);
                af[mt][1] = __float_as_uint(sA[(r + 8) * AV2A_STR + k8 + t]);
                af[mt][2] = __float_as_uint(sA[r * AV2A_STR + k8 + 4 + t]);
                af[mt][3] = __float_as_uint(sA[(r + 8) * AV2A_STR + k8 + 4 + t]);
            }
            uint32_t bf[8][2];
#pragma unroll
            for (int nt = 0; nt < 8; nt++) {
                const int n = nt * 8 + g;
                bf[nt][0] = __float_as_uint(sB[(k8 + t) * AV2B_STR + n]);
                bf[nt][1] = __float_as_uint(sB[(k8 + 4 + t) * AV2B_STR + n]);
            }
#pragma unroll
            for (int mt = 0; mt < 4; mt++)
#pragma unroll
                for (int nt = 0; nt < 8; nt++)
                    mma_tf32(acc[mt][nt], af[mt][0], af[mt][1], af[mt][2], af[mt][3],
                             bf[nt][0], bf[nt][1]);
        }
    }

#pragma unroll
    for (int mt = 0; mt < 4; mt++) {
        const int ra = row0 + wm + mt * 16 + g;
#pragma unroll
        for (int nt = 0; nt < 8; nt++) {
            const int cc = nt * 8 + 2 * t;
            float* dst0 = ctx + (size_t)(b * SS + ra) * DD + h * DH + cc;
            float* dst1 = ctx + (size_t)(b * SS + ra + 8) * DD + h * DH + cc;
            *(float2*)dst0 = make_float2(rnd_tf32(acc[mt][nt][0]), rnd_tf32(acc[mt][nt][1]));
            *(float2*)dst1 = make_float2(rnd_tf32(acc[mt][nt][2]), rnd_tf32(acc[mt][nt][3]));
        }
    }
}

// ============================================================================
// Softmax: warp-per-row (8 rows/block). Full 1024-wide row per warp.
// ============================================================================
__global__ __launch_bounds__(256) void softmax_rows_w(float* __restrict__ w)
{
    const int row = blockIdx.x * 8 + (threadIdx.x >> 5);
    const int lane = threadIdx.x & 31;
    float* p = w + (size_t)row * SS;

    float4 v[8];
#pragma unroll
    for (int j = 0; j < 8; j++)
        v[j] = *(const float4*)(p + lane * 4 + j * 128);

    float m = -1e30f;
#pragma unroll
    for (int j = 0; j < 8; j++)
        m = fmaxf(m, fmaxf(fmaxf(v[j].x, v[j].y), fmaxf(v[j].z, v[j].w)));
#pragma unroll
    for (int o = 16; o; o >>= 1) m = fmaxf(m, __shfl_xor_sync(0xffffffffu, m, o));

    float s = 0.f;
#pragma unroll
    for (int j = 0; j < 8; j++) {
        v[j].x = __expf(v[j].x - m); v[j].y = __expf(v[j].y - m);
        v[j].z = __expf(v[j].z - m); v[j].w = __expf(v[j].w - m);
        s += (v[j].x + v[j].y) + (v[j].z + v[j].w);
    }
#pragma unroll
    for (int o = 16; o; o >>= 1) s += __shfl_xor_sync(0xffffffffu, s, o);
    const float inv = 1.f / s;

#pragma unroll
    for (int j = 0; j < 8; j++) {
        float4 o4;
        o4.x = rnd_tf32(v[j].x * inv); o4.y = rnd_tf32(v[j].y * inv);
        o4.z = rnd_tf32(v[j].z * inv); o4.w = rnd_tf32(v[j].w * inv);
        *(float4*)(p + lane * 4 + j * 128) = o4;
    }
}

// ============================================================================
// Fused residual add + LayerNorm; optional tf32-rounded twin output.
// ============================================================================
__global__ __launch_bounds__(256) void add_ln(
    const float* __restrict__ a, const float* __restrict__ r,
    const float* __restrict__ g, const float* __restrict__ beta,
    float* __restrict__ out, float* __restrict__ outr)
{
    const size_t base = (size_t)blockIdx.x * DD;
    const int tid = threadIdx.x;
    float4 va = *(const float4*)(a + base + tid * 4);
    float4 vr = *(const float4*)(r + base + tid * 4);
    float x0 = va.x + vr.x, x1 = va.y + vr.y, x2 = va.z + vr.z, x3 = va.w + vr.w;

    float s = x0 + x1 + x2 + x3;
    float sq = x0 * x0 + x1 * x1 + x2 * x2 + x3 * x3;
#pragma unroll
    for (int o = 16; o; o >>= 1) {
        s  += __shfl_xor_sync(0xffffffffu, s, o);
        sq += __shfl_xor_sync(0xffffffffu, sq, o);
    }
    __shared__ float ss[8], ssq[8];
    if ((tid & 31) == 0) { ss[tid >> 5] = s; ssq[tid >> 5] = sq; }
    __syncthreads();
    float ts = 0.f, tsq = 0.f;
#pragma unroll
    for (int i = 0; i < 8; i++) { ts += ss[i]; tsq += ssq[i]; }
    const float mu = ts * (1.0f / DD);
    const float var = tsq * (1.0f / DD) - mu * mu;
    const float rs = rsqrtf(var + LN_EPS);

    float4 gg = *(const float4*)(g + tid * 4);
    float4 bb = *(const float4*)(beta + tid * 4);
    float4 o4;
    o4.x = (x0 - mu) * rs * gg.x + bb.x;
    o4.y = (x1 - mu) * rs * gg.y + bb.y;
    o4.z = (x2 - mu) * rs * gg.z + bb.z;
    o4.w = (x3 - mu) * rs * gg.w + bb.w;
    *(float4*)(out + base + tid * 4) = o4;
    if (outr) {
        float4 q4;
        q4.x = rnd_tf32(o4.x); q4.y = rnd_tf32(o4.y);
        q4.z = rnd_tf32(o4.z); q4.w = rnd_tf32(o4.w);
        *(float4*)(outr + base + tid * 4) = q4;
    }
}

// ============================================================================
// Host launch
// ============================================================================
extern "C" void kernel_launch(void* const* d_in, const int* in_sizes, int n_in,
                              void* d_out, int out_size)
{
    (void)in_sizes; (void)n_in; (void)out_size;
    const float* x    = (const float*)d_in[0];
    const float* enc  = (const float*)d_in[1];
    const float* pad  = (const float*)d_in[2];
    const float* sub  = (const float*)d_in[3];
    const float* wq1w = (const float*)d_in[4];   const float* wq1b = (const float*)d_in[5];
    const float* wk1w = (const float*)d_in[6];   const float* wk1b = (const float*)d_in[7];
    const float* wv1w = (const float*)d_in[8];   const float* wv1b = (const float*)d_in[9];
    const float* wo1w = (const float*)d_in[10];  const float* wo1b = (const float*)d_in[11];
    const float* wq2w = (const float*)d_in[12];  const float* wq2b = (const float*)d_in[13];
    const float* wk2w = (const float*)d_in[14];  const float* wk2b = (const float*)d_in[15];
    const float* wv2w = (const float*)d_in[16];  const float* wv2b = (const float*)d_in[17];
    const float* wo2w = (const float*)d_in[18];  const float* wo2b = (const float*)d_in[19];
    const float* f1w  = (const float*)d_in[20];  const float* f1b  = (const float*)d_in[21];
    const float* f2w  = (const float*)d_in[22];  const float* f2b  = (const float*)d_in[23];
    const float* ln1g = (const float*)d_in[24];  const float* ln1b = (const float*)d_in[25];
    const float* ln2g = (const float*)d_in[26];  const float* ln2b = (const float*)d_in[27];
    const float* ln3g = (const float*)d_in[28];  const float* ln3b = (const float*)d_in[29];

    static float *q_p, *k_p, *v_p, *k2_p, *v2_p, *ctx_p, *mha_p, *res1_p, *res2_p, *ffn_p;
    static float *wt_p, *xr_p, *encr_p, *res1r_p, *res2r_p;
    static cudaStream_t s1;
    static cudaEvent_t evFork, evKV2;
    static bool init = false;
    if (!init) {
        cudaGetSymbolAddress((void**)&q_p, g_q);
        cudaGetSymbolAddress((void**)&k_p, g_k);
        cudaGetSymbolAddress((void**)&v_p, g_v);
        cudaGetSymbolAddress((void**)&k2_p, g_k2);
        cudaGetSymbolAddress((void**)&v2_p, g_v2);
        cudaGetSymbolAddress((void**)&ctx_p, g_ctx);
        cudaGetSymbolAddress((void**)&mha_p, g_mha);
        cudaGetSymbolAddress((void**)&res1_p, g_res1);
        cudaGetSymbolAddress((void**)&res2_p, g_res2);
        cudaGetSymbolAddress((void**)&ffn_p, g_ffn);
        cudaGetSymbolAddress((void**)&wt_p, g_wt);
        cudaGetSymbolAddress((void**)&xr_p, g_xr);
        cudaGetSymbolAddress((void**)&encr_p, g_encr);
        cudaGetSymbolAddress((void**)&res1r_p, g_res1r);
        cudaGetSymbolAddress((void**)&res2r_p, g_res2r);
        cudaStreamCreateWithFlags(&s1, cudaStreamNonBlocking);
        cudaEventCreateWithFlags(&evFork, cudaEventDisableTiming);
        cudaEventCreateWithFlags(&evKV2, cudaEventDisableTiming);
        cudaFuncSetAttribute(gemm_ca<false>,
            cudaFuncAttributeMaxDynamicSharedMemorySize, GEMM_SMEM_BYTES);
        cudaFuncSetAttribute(gemm_ca<true>,
            cudaFuncAttributeMaxDynamicSharedMemorySize, GEMM_SMEM_BYTES);
        cudaFuncSetAttribute(gemm_qkv,
            cudaFuncAttributeMaxDynamicSharedMemorySize, GEMM_SMEM_BYTES);
        cudaFuncSetAttribute(attn_logits4,
            cudaFuncAttributeMaxDynamicSharedMemorySize, LOG_SMEM_BYTES);
        cudaFuncSetAttribute(attn_av2,
            cudaFuncAttributeMaxDynamicSharedMemorySize, AV_SMEM_BYTES);
        init = true;
    }

    // rounded weight slots (floats)
    const size_t M1 = 1024u * 1024u;
    float* t_q1 = wt_p + 0*M1;  float* t_k1 = wt_p + 1*M1;
    float* t_v1 = wt_p + 2*M1;  float* t_o1 = wt_p + 3*M1;
    float* t_q2 = wt_p + 4*M1;  float* t_k2 = wt_p + 5*M1;
    float* t_v2 = wt_p + 6*M1;  float* t_o2 = wt_p + 7*M1;
    float* t_f1 = wt_p + 8*M1;
    float* t_f2 = wt_p + 12*M1;

    // Output layout: out3 | attn_w1 | attn_w2
    float* out3 = (float*)d_out;
    float* aw1  = out3 + (size_t)MM * DD;
    float* aw2  = aw1 + (size_t)BB * HH * SS * SS;

    // ---- merged rounding (one launch) ----
    R12 r12;
    const float* srcs[12] = {wq1w, wk1w, wv1w, wo1w, wq2w, wk2w, wv2w, wo2w,
                             f1w, f2w, x, enc};
    float* dsts[12] = {t_q1, t_k1, t_v1, t_o1, t_q2, t_k2, t_v2, t_o2,
                       t_f1, t_f2, xr_p, encr_p};
    int blks[12] = {256,256,256,256,256,256,256,256,1024,1024,1024,1024};
    int c = 0;
    for (int i = 0; i < 12; i++) {
        r12.src[i] = (const float4*)srcs[i];
        r12.dst[i] = (float4*)dsts[i];
        r12.cum[i] = c;
        c += blks[i];
    }
    r12.cum[12] = c;   // 6144
    round_all<<<c, 256>>>(r12);

    const dim3 gD(DD / 128, MM / 128);
    const dim3 gF(DFF / 128, MM / 128);
    const dim3 gQKV(DD / 128, MM / 128, 3);
    const dim3 gKV2(DD / 128, MM / 128, 2);
    const dim3 gLog(SS / 128, BB * HH);
    const dim3 gAV(SS / 256, BB * HH);
    const int nSmBlocks = BB * HH * SS / 8;   // 8192

    // ---- fork: K2/V2 projections on side stream (depend only on encr) ----
    cudaEventRecord(evFork, 0);
    cudaStreamWaitEvent(s1, evFork, 0);
    {
        QKV qk;
        qk.A[0] = encr_p; qk.A[1] = encr_p; qk.A[2] = encr_p;
        qk.W[0] = t_k2; qk.W[1] = t_v2; qk.W[2] = t_v2;
        qk.b[0] = wk2b; qk.b[1] = wv2b; qk.b[2] = wv2b;
        qk.C[0] = k2_p; qk.C[1] = v2_p; qk.C[2] = v2_p;
        qk.round_flag[0] = 1; qk.round_flag[1] = 1; qk.round_flag[2] = 1;
        gemm_qkv<<<gKV2, 128, GEMM_SMEM_BYTES, s1>>>(qk);
    }
    cudaEventRecord(evKV2, s1);

    // ---- MHA1 (self-attention) on main stream ----
    {
        QKV qk;
        qk.A[0] = xr_p; qk.A[1] = xr_p; qk.A[2] = xr_p;
        qk.W[0] = t_q1; qk.W[1] = t_k1; qk.W[2] = t_v1;
        qk.b[0] = wq1b; qk.b[1] = wk1b; qk.b[2] = wv1b;
        qk.C[0] = q_p;  qk.C[1] = k_p;  qk.C[2] = v_p;
        qk.round_flag[0] = 1; qk.round_flag[1] = 1; qk.round_flag[2] = 1;
        gemm_qkv<<<gQKV, 128, GEMM_SMEM_BYTES>>>(qk);
    }
    attn_logits4<<<gLog, 128, LOG_SMEM_BYTES>>>(q_p, k_p, sub, aw1);
    softmax_rows_w<<<nSmBlocks, 256>>>(aw1);
    attn_av2<<<gAV, 128, AV_SMEM_BYTES>>>(aw1, v_p, ctx_p);
    gemm_ca<false><<<gD, 128, GEMM_SMEM_BYTES>>>(ctx_p, t_o1, wo1b, mha_p, DD, DD, 0);
    add_ln<<<MM, 256>>>(mha_p, x, ln1g, ln1b, res1_p, res1r_p);

    // ---- MHA2 (cross-attention) ----
    gemm_ca<false><<<gD, 128, GEMM_SMEM_BYTES>>>(res1r_p, t_q2, wq2b, q_p, DD, DD, 1);
    cudaStreamWaitEvent(0, evKV2, 0);   // join: k2/v2 ready
    attn_logits4<<<gLog, 128, LOG_SMEM_BYTES>>>(q_p, k2_p, pad, aw2);
    softmax_rows_w<<<nSmBlocks, 256>>>(aw2);
    attn_av2<<<gAV, 128, AV_SMEM_BYTES>>>(aw2, v2_p, ctx_p);
    gemm_ca<false><<<gD, 128, GEMM_SMEM_BYTES>>>(ctx_p, t_o2, wo2b, mha_p, DD, DD, 0);
    add_ln<<<MM, 256>>>(mha_p, res1_p, ln2g, ln2b, res2_p, res2r_p);

    // ---- FFN ----
    gemm_ca<true ><<<gF, 128, GEMM_SMEM_BYTES>>>(res2r_p, t_f1, f1b, ffn_p, DFF, DD, 1);
    gemm_ca<false><<<gD, 128, GEMM_SMEM_BYTES>>>(ffn_p, t_f2, f2b, mha_p, DD, DFF, 0);
    add_ln<<<MM, 256>>>(mha_p, res2_p, ln3g, ln3b, out3, nullptr);
}

// round 15
// speedup vs baseline: 1.0270x; 1.0270x over previous
#include <cuda_runtime.h>
#include <cstdint>
#include <math.h>

// Problem constants
#define BB   4
#define SS   1024
#define DD   1024
#define HH   16
#define DH   64
#define DFF  4096
#define MM   (BB*SS)          // 4096 rows
#define LN_EPS 1e-5f

// -------------------- scratch (static device globals; no runtime alloc) ----
__device__ float g_q[MM*DD];
__device__ float g_k[MM*DD];
__device__ float g_v[MM*DD];
__device__ float g_k2[MM*DD];
__device__ float g_v2[MM*DD];
__device__ float g_ctx[MM*DD];
__device__ float g_mha[MM*DD];
__device__ float g_res1[MM*DD];
__device__ float g_res2[MM*DD];
__device__ float g_ffn[(size_t)MM*DFF];
__device__ float g_wt[16u*1024u*1024u];   // tf32-rounded weights (concatenated)
__device__ float g_xr[MM*DD];
__device__ float g_encr[MM*DD];
__device__ float g_res1r[MM*DD];
__device__ float g_res2r[MM*DD];

__device__ __forceinline__ uint32_t cvt_tf32(float f) {
    uint32_t r;
    asm("cvt.rna.tf32.f32 %0, %1;" : "=r"(r) : "f"(f));
    return r;
}
__device__ __forceinline__ float rnd_tf32(float f) {
    return __uint_as_float(cvt_tf32(f));
}
__device__ __forceinline__ uint32_t smem_u32(const void* p) {
    uint32_t a;
    asm("{ .reg .u64 t; cvta.to.shared.u64 t, %1; cvt.u32.u64 %0, t; }"
        : "=r"(a) : "l"(p));
    return a;
}
__device__ __forceinline__ void cp16(uint32_t dst, const void* src) {
    asm volatile("cp.async.ca.shared.global [%0], [%1], 16;" :: "r"(dst), "l"(src));
}
#define CP_COMMIT() asm volatile("cp.async.commit_group;")
#define CP_WAIT0()  asm volatile("cp.async.wait_group 0;")

__device__ __forceinline__ void mma_tf32(float* c,
    uint32_t a0, uint32_t a1, uint32_t a2, uint32_t a3,
    uint32_t b0, uint32_t b1)
{
    asm volatile(
        "mma.sync.aligned.m16n8k8.row.col.f32.tf32.tf32.f32 "
        "{%0,%1,%2,%3}, {%4,%5,%6,%7}, {%8,%9}, {%0,%1,%2,%3};"
        : "+f"(c[0]), "+f"(c[1]), "+f"(c[2]), "+f"(c[3])
        : "r"(a0), "r"(a1), "r"(a2), "r"(a3), "r"(b0), "r"(b1));
}

// ============================================================================
// Merged tf32 rounding: 12 tensors, one launch. Each block = 4096 floats.
// ============================================================================
struct R12 {
    const float4* src[12];
    float4* dst[12];
    int cum[13];
};

__global__ __launch_bounds__(256) void round_all(R12 r)
{
    const int bid = blockIdx.x;
    int ti = 0;
#pragma unroll
    for (int i = 0; i < 12; i++)
        if (bid >= r.cum[i + 1]) ti = i + 1;
    const float4* s = r.src[ti];
    float4* d = r.dst[ti];
    const int base = (bid - r.cum[ti]) * 1024 + threadIdx.x;
#pragma unroll
    for (int j = 0; j < 4; j++) {
        const int idx = base + j * 256;
        float4 v = s[idx];
        float4 o;
        o.x = rnd_tf32(v.x); o.y = rnd_tf32(v.y);
        o.z = rnd_tf32(v.z); o.w = rnd_tf32(v.w);
        d[idx] = o;
    }
}

// ============================================================================
// GEMM body: C = A@W + bias. CTA 128x128, BK=32, 128 threads = 4 warps (2x2),
// warp tile 64x64. 2-stage pipeline: wait0 -> sync -> issue-next -> compute.
// ============================================================================
#define AS_STR 36
#define BS_STR 136
#define A_FLTS (128*AS_STR)
#define B_FLTS (32*BS_STR)
#define BUF_FLTS (A_FLTS + B_FLTS)       // 8960
#define GEMM_SMEM_BYTES (2*BUF_FLTS*4)   // 71680

template<bool RELU>
__device__ __forceinline__ void gemm_body(
    const float* __restrict__ A, const float* __restrict__ W,
    const float* __restrict__ bias, float* __restrict__ C,
    int N, int K, bool round_out,
    float* sm, int row0, int col0)
{
    const uint32_t smb = smem_u32(sm);
    const int tid = threadIdx.x;              // 0..127
    const int wid = tid >> 5, lane = tid & 31;
    const int g = lane >> 2, t = lane & 3;
    const int wm = (wid >> 1) * 64;           // 2x2 warp grid, 64x64 tiles
    const int wn = (wid & 1) * 64;

    int a_row[8], a_c4[8], b_k[8], b_n4[8];
#pragma unroll
    for (int it = 0; it < 8; it++) {
        int lin = it * 128 + tid;
        a_row[it] = lin >> 3;
        a_c4[it]  = (lin & 7) * 4;
        b_k[it]   = lin >> 5;
        b_n4[it]  = (lin & 31) * 4;
    }

    float acc[4][8][4];
#pragma unroll
    for (int mt = 0; mt < 4; mt++)
#pragma unroll
        for (int nt = 0; nt < 8; nt++)
#pragma unroll
            for (int i = 0; i < 4; i++) acc[mt][nt][i] = 0.f;

    const int nchunk = K >> 5;

    {
        const uint32_t ab = smb, bb = smb + A_FLTS * 4;
#pragma unroll
        for (int it = 0; it < 8; it++) {
            cp16(ab + (a_row[it] * AS_STR + a_c4[it]) * 4,
                 A + (size_t)(row0 + a_row[it]) * K + a_c4[it]);
            cp16(bb + (b_k[it] * BS_STR + b_n4[it]) * 4,
                 W + (size_t)b_k[it] * N + col0 + b_n4[it]);
        }
        CP_COMMIT();
    }

    for (int ic = 0; ic < nchunk; ic++) {
        const int p = ic & 1;
        CP_WAIT0();
        __syncthreads();
        if (ic + 1 < nchunk) {
            const int k1 = (ic + 1) << 5;
            const uint32_t ab = smb + (p ? 0 : BUF_FLTS * 4);
            const uint32_t bb = ab + A_FLTS * 4;
#pragma unroll
            for (int it = 0; it < 8; it++) {
                cp16(ab + (a_row[it] * AS_STR + a_c4[it]) * 4,
                     A + (size_t)(row0 + a_row[it]) * K + k1 + a_c4[it]);
                cp16(bb + (b_k[it] * BS_STR + b_n4[it]) * 4,
                     W + (size_t)(k1 + b_k[it]) * N + col0 + b_n4[it]);
            }
            CP_COMMIT();
        }

        const float* sA = sm + (p ? BUF_FLTS : 0);
        const float* sB = sA + A_FLTS;
#pragma unroll
        for (int ks = 0; ks < 4; ks++) {
            const int k8 = ks * 8;
            uint32_t af[4][4];
#pragma unroll
            for (int mt = 0; mt < 4; mt++) {
                const int r = wm + mt * 16 + g;
                af[mt][0] = __float_as_uint(sA[r * AS_STR + k8 + t]);
                af[mt][1] = __float_as_uint(sA[(r + 8) * AS_STR + k8 + t]);
                af[mt][2] = __float_as_uint(sA[r * AS_STR + k8 + 4 + t]);
                af[mt][3] = __float_as_uint(sA[(r + 8) * AS_STR + k8 + 4 + t]);
            }
            uint32_t bf[8][2];
#pragma unroll
            for (int nt = 0; nt < 8; nt++) {
                const int n = wn + nt * 8 + g;
                bf[nt][0] = __float_as_uint(sB[(k8 + t) * BS_STR + n]);
                bf[nt][1] = __float_as_uint(sB[(k8 + 4 + t) * BS_STR + n]);
            }
#pragma unroll
            for (int mt = 0; mt < 4; mt++)
#pragma unroll
                for (int nt = 0; nt < 8; nt++)
                    mma_tf32(acc[mt][nt], af[mt][0], af[mt][1], af[mt][2], af[mt][3],
                             bf[nt][0], bf[nt][1]);
        }
    }

#pragma unroll
    for (int mt = 0; mt < 4; mt++) {
        const int ra = row0 + wm + mt * 16 + g;
#pragma unroll
        for (int nt = 0; nt < 8; nt++) {
            const int cc = col0 + wn + nt * 8 + 2 * t;
            float2 bv = *(const float2*)(bias + cc);
            float v0 = acc[mt][nt][0] + bv.x;
            float v1 = acc[mt][nt][1] + bv.y;
            float v2 = acc[mt][nt][2] + bv.x;
            float v3 = acc[mt][nt][3] + bv.y;
            if (RELU) {
                v0 = fmaxf(v0, 0.f); v1 = fmaxf(v1, 0.f);
                v2 = fmaxf(v2, 0.f); v3 = fmaxf(v3, 0.f);
            }
            if (round_out) {
                v0 = rnd_tf32(v0); v1 = rnd_tf32(v1);
                v2 = rnd_tf32(v2); v3 = rnd_tf32(v3);
            }
            *(float2*)(C + (size_t)ra * N + cc) = make_float2(v0, v1);
            *(float2*)(C + (size_t)(ra + 8) * N + cc) = make_float2(v2, v3);
        }
    }
}

template<bool RELU>
__global__ void __launch_bounds__(128, 2) gemm_ca(
    const float* __restrict__ A, const float* __restrict__ W,
    const float* __restrict__ bias, float* __restrict__ C,
    int N, int K, int round_out)
{
    extern __shared__ float sm[];
    gemm_body<RELU>(A, W, bias, C, N, K, round_out != 0,
                    sm, blockIdx.y * 128, blockIdx.x * 128);
}

// Batched projections: z selects (A, W, bias, C, round flag). Up to 3 slots.
struct QKV {
    const float* A[3];
    const float* W[3];
    const float* b[3];
    float* C[3];
    int round_flag[3];
};

__global__ void __launch_bounds__(128, 2) gemm_qkv(QKV q)
{
    extern __shared__ float sm[];
    const int z = blockIdx.z;
    gemm_body<false>(q.A[z], q.W[z], q.b[z], q.C[z], DD, DD,
                     q.round_flag[z] != 0, sm, blockIdx.y * 128, blockIdx.x * 128);
}

// ============================================================================
// Attention logits (single tf32, one-shot — best measured variant, R12):
// out = QK^T/8 + mask. Q and K both pre-rounded tf32, cp.async'd raw.
// CTA 128x128 per (bh), K=64 one shot. 128 thr = 4 warps of 64x64.
// SMEM 69.6KB -> 3 CTAs/SM.
// ============================================================================
#define L3_STR 68
#define L3_TILE (128*L3_STR)              // floats per tile
#define LOG_SMEM_BYTES (2*L3_TILE*4)      // 69632

__global__ void __launch_bounds__(128, 3) attn_logits3(
    const float* __restrict__ q, const float* __restrict__ k,
    const float* __restrict__ mask, float* __restrict__ out)
{
    extern __shared__ float sm[];
    float* Qs = sm;
    float* Ks = sm + L3_TILE;
    const uint32_t qs_u32 = smem_u32(Qs);
    const uint32_t ks_u32 = smem_u32(Ks);

    const int tid = threadIdx.x;              // 0..127
    const int wid = tid >> 5, lane = tid & 31;
    const int g = lane >> 2, t = lane & 3;
    const int wm = (wid >> 1) * 64;
    const int wn = (wid & 1) * 64;

    const int bh = blockIdx.z;
    const int b = bh >> 4, h = bh & 15;
    const int row0 = blockIdx.y * 128, col0 = blockIdx.x * 128;
    const float* qb = q + (size_t)b * SS * DD + h * DH;
    const float* kb = k + (size_t)b * SS * DD + h * DH;

    // load Q [128 rows][64 k] and K [128 n][64 k], both k-contiguous
#pragma unroll
    for (int it = 0; it < 16; it++) {
        const int lin = it * 128 + tid;
        const int r = lin >> 4, c4 = (lin & 15) * 4;
        cp16(qs_u32 + (r * L3_STR + c4) * 4,
             qb + (size_t)(row0 + r) * DD + c4);
        cp16(ks_u32 + (r * L3_STR + c4) * 4,
             kb + (size_t)(col0 + r) * DD + c4);
    }
    CP_COMMIT();
    CP_WAIT0();
    __syncthreads();

    float acc[4][8][4];
#pragma unroll
    for (int mt = 0; mt < 4; mt++)
#pragma unroll
        for (int nt = 0; nt < 8; nt++)
#pragma unroll
            for (int i = 0; i < 4; i++) acc[mt][nt][i] = 0.f;

#pragma unroll
    for (int ks = 0; ks < 8; ks++) {
        const int k8 = ks * 8;
        uint32_t af[4][4];
#pragma unroll
        for (int mt = 0; mt < 4; mt++) {
            const int r = wm + mt * 16 + g;
            af[mt][0] = __float_as_uint(Qs[r * L3_STR + k8 + t]);
            af[mt][1] = __float_as_uint(Qs[(r + 8) * L3_STR + k8 + t]);
            af[mt][2] = __float_as_uint(Qs[r * L3_STR + k8 + 4 + t]);
            af[mt][3] = __float_as_uint(Qs[(r + 8) * L3_STR + k8 + 4 + t]);
        }
        uint32_t bf[8][2];
#pragma unroll
        for (int nt = 0; nt < 8; nt++) {
            const int n = wn + nt * 8 + g;
            bf[nt][0] = __float_as_uint(Ks[n * L3_STR + k8 + t]);
            bf[nt][1] = __float_as_uint(Ks[n * L3_STR + k8 + 4 + t]);
        }
#pragma unroll
        for (int mt = 0; mt < 4; mt++)
#pragma unroll
            for (int nt = 0; nt < 8; nt++)
                mma_tf32(acc[mt][nt], af[mt][0], af[mt][1], af[mt][2], af[mt][3],
                         bf[nt][0], bf[nt][1]);
    }

    const float* mb = mask + (size_t)b * SS * SS;
    float* ob = out + (size_t)bh * SS * SS;
#pragma unroll
    for (int mt = 0; mt < 4; mt++) {
        const int r = row0 + wm + mt * 16 + g;
#pragma unroll
        for (int nt = 0; nt < 8; nt++) {
            const int c = col0 + wn + nt * 8 + 2 * t;
            float2 m0 = *(const float2*)(mb + (size_t)r * SS + c);
            float2 m1 = *(const float2*)(mb + (size_t)(r + 8) * SS + c);
            *(float2*)(ob + (size_t)r * SS + c) =
                make_float2(acc[mt][nt][0] * 0.125f + m0.x,
                            acc[mt][nt][1] * 0.125f + m0.y);
            *(float2*)(ob + (size_t)(r + 8) * SS + c) =
                make_float2(acc[mt][nt][2] * 0.125f + m1.x,
                            acc[mt][nt][3] * 0.125f + m1.y);
        }
    }
}

// ============================================================================
// Batched AV v2: CTA 256x64, 128 threads = 4 warps of 64x64 (LDS/MMA = 1.0).
// 2-stage cp.async pipeline over 32 k-chunks.
// ============================================================================
#define AV2A_STR 36
#define AV2B_STR 72
#define AV2_A_FLTS (256*AV2A_STR)          // 9216
#define AV2_B_FLTS (32*AV2B_STR)           // 2304
#define AV2_BUF (AV2_A_FLTS + AV2_B_FLTS)  // 11520
#define AV_SMEM_BYTES (2*AV2_BUF*4)        // 92160

__global__ void __launch_bounds__(128, 2) attn_av2(
    const float* __restrict__ w, const float* __restrict__ v,
    float* __restrict__ ctx)
{
    extern __shared__ float sm[];
    const uint32_t smb = smem_u32(sm);
    const int tid = threadIdx.x;              // 0..127
    const int wid = tid >> 5, lane = tid & 31;
    const int g = lane >> 2, t = lane & 3;
    const int wm = wid * 64;                  // 4 warps stacked in M

    const int bh = blockIdx.y;
    const int b = bh >> 4, h = bh & 15;
    const int row0 = blockIdx.x * 256;
    const float* wb = w + (size_t)bh * SS * SS;
    const float* vb = v + (size_t)b * SS * DD + h * DH;

    int a_row[16], a_c4[16], b_k[4], b_n4[4];
#pragma unroll
    for (int it = 0; it < 16; it++) {
        int lin = it * 128 + tid;
        a_row[it] = lin >> 3;                 // 0..255
        a_c4[it]  = (lin & 7) * 4;            // 0..28
    }
#pragma unroll
    for (int it = 0; it < 4; it++) {
        int lin = it * 128 + tid;
        b_k[it]  = lin >> 4;                  // 0..31
        b_n4[it] = (lin & 15) * 4;            // 0..60
    }

    float acc[4][8][4];
#pragma unroll
    for (int mt = 0; mt < 4; mt++)
#pragma unroll
        for (int nt = 0; nt < 8; nt++)
#pragma unroll
            for (int i = 0; i < 4; i++) acc[mt][nt][i] = 0.f;

    {
        const uint32_t ab = smb, bb = smb + AV2_A_FLTS * 4;
#pragma unroll
        for (int it = 0; it < 16; it++)
            cp16(ab + (a_row[it] * AV2A_STR + a_c4[it]) * 4,
                 wb + (size_t)(row0 + a_row[it]) * SS + a_c4[it]);
#pragma unroll
        for (int it = 0; it < 4; it++)
            cp16(bb + (b_k[it] * AV2B_STR + b_n4[it]) * 4,
                 vb + (size_t)b_k[it] * DD + b_n4[it]);
        CP_COMMIT();
    }

    for (int ic = 0; ic < 32; ic++) {
        const int p = ic & 1;
        CP_WAIT0();
        __syncthreads();
        if (ic + 1 < 32) {
            const int k1 = (ic + 1) << 5;
            const uint32_t ab = smb + (p ? 0 : AV2_BUF * 4);
            const uint32_t bb = ab + AV2_A_FLTS * 4;
#pragma unroll
            for (int it = 0; it < 16; it++)
                cp16(ab + (a_row[it] * AV2A_STR + a_c4[it]) * 4,
                     wb + (size_t)(row0 + a_row[it]) * SS + k1 + a_c4[it]);
#pragma unroll
            for (int it = 0; it < 4; it++)
                cp16(bb + (b_k[it] * AV2B_STR + b_n4[it]) * 4,
                     vb + (size_t)(k1 + b_k[it]) * DD + b_n4[it]);
            CP_COMMIT();
        }

        const float* sA = sm + (p ? AV2_BUF : 0);
        const float* sB = sA + AV2_A_FLTS;
#pragma unroll
        for (int ks = 0; ks < 4; ks++) {
            const int k8 = ks * 8;
            uint32_t af[4][4];
#pragma unroll
            for (int mt = 0; mt < 4; mt++) {
                const int r = wm + mt * 16 + g;
                af[mt][0] = __float_as_uint(sA[r * AV2A_STR + k8 + t]);
                af[mt][1] = __float_as_uint(sA[(r + 8) * AV2A_STR + k8 + t]);
                af[mt][2] = __float_as_uint(sA[r * AV2A_STR + k8 + 4 + t]);
                af[mt][3] = __float_as_uint(sA[(r + 8) * AV2A_STR + k8 + 4 + t]);
            }
            uint32_t bf[8][2];
#pragma unroll
            for (int nt = 0; nt < 8; nt++) {
                const int n = nt * 8 + g;
                bf[nt][0] = __float_as_uint(sB[(k8 + t) * AV2B_STR + n]);
                bf[nt][1] = __float_as_uint(sB[(k8 + 4 + t) * AV2B_STR + n]);
            }
#pragma unroll
            for (int mt = 0; mt < 4; mt++)
#pragma unroll
                for (int nt = 0; nt < 8; nt++)
                    mma_tf32(acc[mt][nt], af[mt][0], af[mt][1], af[mt][2], af[mt][3],
                             bf[nt][0], bf[nt][1]);
        }
    }

#pragma unroll
    for (int mt = 0; mt < 4; mt++) {
        const int ra = row0 + wm + mt * 16 + g;
#pragma unroll
        for (int nt = 0; nt < 8; nt++) {
            const int cc = nt * 8 + 2 * t;
            float* dst0 = ctx + (size_t)(b * SS + ra) * DD + h * DH + cc;
            float* dst1 = ctx + (size_t)(b * SS + ra + 8) * DD + h * DH + cc;
            *(float2*)dst0 = make_float2(rnd_tf32(acc[mt][nt][0]), rnd_tf32(acc[mt][nt][1]));
            *(float2*)dst1 = make_float2(rnd_tf32(acc[mt][nt][2]), rnd_tf32(acc[mt][nt][3]));
        }
    }
}

// ============================================================================
// Softmax: warp-per-row (8 rows/block). Full 1024-wide row per warp.
// ============================================================================
__global__ __launch_bounds__(256) void softmax_rows_w(float* __restrict__ w)
{
    const int row = blockIdx.x * 8 + (threadIdx.x >> 5);
    const int lane = threadIdx.x & 31;
    float* p = w + (size_t)row * SS;

    float4 v[8];
#pragma unroll
    for (int j = 0; j < 8; j++)
        v[j] = *(const float4*)(p + lane * 4 + j * 128);

    float m = -1e30f;
#pragma unroll
    for (int j = 0; j < 8; j++)
        m = fmaxf(m, fmaxf(fmaxf(v[j].x, v[j].y), fmaxf(v[j].z, v[j].w)));
#pragma unroll
    for (int o = 16; o; o >>= 1) m = fmaxf(m, __shfl_xor_sync(0xffffffffu, m, o));

    float s = 0.f;
#pragma unroll
    for (int j = 0; j < 8; j++) {
        v[j].x = __expf(v[j].x - m); v[j].y = __expf(v[j].y - m);
        v[j].z = __expf(v[j].z - m); v[j].w = __expf(v[j].w - m);
        s += (v[j].x + v[j].y) + (v[j].z + v[j].w);
    }
#pragma unroll
    for (int o = 16; o; o >>= 1) s += __shfl_xor_sync(0xffffffffu, s, o);
    const float inv = 1.f / s;

#pragma unroll
    for (int j = 0; j < 8; j++) {
        float4 o4;
        o4.x = rnd_tf32(v[j].x * inv); o4.y = rnd_tf32(v[j].y * inv);
        o4.z = rnd_tf32(v[j].z * inv); o4.w = rnd_tf32(v[j].w * inv);
        *(float4*)(p + lane * 4 + j * 128) = o4;
    }
}

// ============================================================================
// Fused residual add + LayerNorm; optional tf32-rounded twin output.
// ============================================================================
__global__ __launch_bounds__(256) void add_ln(
    const float* __restrict__ a, const float* __restrict__ r,
    const float* __restrict__ g, const float* __restrict__ beta,
    float* __restrict__ out, float* __restrict__ outr)
{
    const size_t base = (size_t)blockIdx.x * DD;
    const int tid = threadIdx.x;
    float4 va = *(const float4*)(a + base + tid * 4);
    float4 vr = *(const float4*)(r + base + tid * 4);
    float x0 = va.x + vr.x, x1 = va.y + vr.y, x2 = va.z + vr.z, x3 = va.w + vr.w;

    float s = x0 + x1 + x2 + x3;
    float sq = x0 * x0 + x1 * x1 + x2 * x2 + x3 * x3;
#pragma unroll
    for (int o = 16; o; o >>= 1) {
        s  += __shfl_xor_sync(0xffffffffu, s, o);
        sq += __shfl_xor_sync(0xffffffffu, sq, o);
    }
    __shared__ float ss[8], ssq[8];
    if ((tid & 31) == 0) { ss[tid >> 5] = s; ssq[tid >> 5] = sq; }
    __syncthreads();
    float ts = 0.f, tsq = 0.f;
#pragma unroll
    for (int i = 0; i < 8; i++) { ts += ss[i]; tsq += ssq[i]; }
    const float mu = ts * (1.0f / DD);
    const float var = tsq * (1.0f / DD) - mu * mu;
    const float rs = rsqrtf(var + LN_EPS);

    float4 gg = *(const float4*)(g + tid * 4);
    float4 bb = *(const float4*)(beta + tid * 4);
    float4 o4;
    o4.x = (x0 - mu) * rs * gg.x + bb.x;
    o4.y = (x1 - mu) * rs * gg.y + bb.y;
    o4.z = (x2 - mu) * rs * gg.z + bb.z;
    o4.w = (x3 - mu) * rs * gg.w + bb.w;
    *(float4*)(out + base + tid * 4) = o4;
    if (outr) {
        float4 q4;
        q4.x = rnd_tf32(o4.x); q4.y = rnd_tf32(o4.y);
        q4.z = rnd_tf32(o4.z); q4.w = rnd_tf32(o4.w);
        *(float4*)(outr + base + tid * 4) = q4;
    }
}

// ============================================================================
// Host launch
// ============================================================================
extern "C" void kernel_launch(void* const* d_in, const int* in_sizes, int n_in,
                              void* d_out, int out_size)
{
    (void)in_sizes; (void)n_in; (void)out_size;
    const float* x    = (const float*)d_in[0];
    const float* enc  = (const float*)d_in[1];
    const float* pad  = (const float*)d_in[2];
    const float* sub  = (const float*)d_in[3];
    const float* wq1w = (const float*)d_in[4];   const float* wq1b = (const float*)d_in[5];
    const float* wk1w = (const float*)d_in[6];   const float* wk1b = (const float*)d_in[7];
    const float* wv1w = (const float*)d_in[8];   const float* wv1b = (const float*)d_in[9];
    const float* wo1w = (const float*)d_in[10];  const float* wo1b = (const float*)d_in[11];
    const float* wq2w = (const float*)d_in[12];  const float* wq2b = (const float*)d_in[13];
    const float* wk2w = (const float*)d_in[14];  const float* wk2b = (const float*)d_in[15];
    const float* wv2w = (const float*)d_in[16];  const float* wv2b = (const float*)d_in[17];
    const float* wo2w = (const float*)d_in[18];  const float* wo2b = (const float*)d_in[19];
    const float* f1w  = (const float*)d_in[20];  const float* f1b  = (const float*)d_in[21];
    const float* f2w  = (const float*)d_in[22];  const float* f2b  = (const float*)d_in[23];
    const float* ln1g = (const float*)d_in[24];  const float* ln1b = (const float*)d_in[25];
    const float* ln2g = (const float*)d_in[26];  const float* ln2b = (const float*)d_in[27];
    const float* ln3g = (const float*)d_in[28];  const float* ln3b = (const float*)d_in[29];

    static float *q_p, *k_p, *v_p, *k2_p, *v2_p, *ctx_p, *mha_p, *res1_p, *res2_p, *ffn_p;
    static float *wt_p, *xr_p, *encr_p, *res1r_p, *res2r_p;
    static cudaStream_t s1;
    static cudaEvent_t evFork, evKV2;
    static bool init = false;
    if (!init) {
        cudaGetSymbolAddress((void**)&q_p, g_q);
        cudaGetSymbolAddress((void**)&k_p, g_k);
        cudaGetSymbolAddress((void**)&v_p, g_v);
        cudaGetSymbolAddress((void**)&k2_p, g_k2);
        cudaGetSymbolAddress((void**)&v2_p, g_v2);
        cudaGetSymbolAddress((void**)&ctx_p, g_ctx);
        cudaGetSymbolAddress((void**)&mha_p, g_mha);
        cudaGetSymbolAddress((void**)&res1_p, g_res1);
        cudaGetSymbolAddress((void**)&res2_p, g_res2);
        cudaGetSymbolAddress((void**)&ffn_p, g_ffn);
        cudaGetSymbolAddress((void**)&wt_p, g_wt);
        cudaGetSymbolAddress((void**)&xr_p, g_xr);
        cudaGetSymbolAddress((void**)&encr_p, g_encr);
        cudaGetSymbolAddress((void**)&res1r_p, g_res1r);
        cudaGetSymbolAddress((void**)&res2r_p, g_res2r);
        cudaStreamCreateWithFlags(&s1, cudaStreamNonBlocking);
        cudaEventCreateWithFlags(&evFork, cudaEventDisableTiming);
        cudaEventCreateWithFlags(&evKV2, cudaEventDisableTiming);
        cudaFuncSetAttribute(gemm_ca<false>,
            cudaFuncAttributeMaxDynamicSharedMemorySize, GEMM_SMEM_BYTES);
        cudaFuncSetAttribute(gemm_ca<true>,
            cudaFuncAttributeMaxDynamicSharedMemorySize, GEMM_SMEM_BYTES);
        cudaFuncSetAttribute(gemm_qkv,
            cudaFuncAttributeMaxDynamicSharedMemorySize, GEMM_SMEM_BYTES);
        cudaFuncSetAttribute(attn_logits3,
            cudaFuncAttributeMaxDynamicSharedMemorySize, LOG_SMEM_BYTES);
        cudaFuncSetAttribute(attn_av2,
            cudaFuncAttributeMaxDynamicSharedMemorySize, AV_SMEM_BYTES);
        init = true;
    }

    // rounded weight slots (floats)
    const size_t M1 = 1024u * 1024u;
    float* t_q1 = wt_p + 0*M1;  float* t_k1 = wt_p + 1*M1;
    float* t_v1 = wt_p + 2*M1;  float* t_o1 = wt_p + 3*M1;
    float* t_q2 = wt_p + 4*M1;  float* t_k2 = wt_p + 5*M1;
    float* t_v2 = wt_p + 6*M1;  float* t_o2 = wt_p + 7*M1;
    float* t_f1 = wt_p + 8*M1;
    float* t_f2 = wt_p + 12*M1;

    // Output layout: out3 | attn_w1 | attn_w2
    float* out3 = (float*)d_out;
    float* aw1  = out3 + (size_t)MM * DD;
    float* aw2  = aw1 + (size_t)BB * HH * SS * SS;

    // ---- merged rounding (one launch) ----
    R12 r12;
    const float* srcs[12] = {wq1w, wk1w, wv1w, wo1w, wq2w, wk2w, wv2w, wo2w,
                             f1w, f2w, x, enc};
    float* dsts[12] = {t_q1, t_k1, t_v1, t_o1, t_q2, t_k2, t_v2, t_o2,
                       t_f1, t_f2, xr_p, encr_p};
    int blks[12] = {256,256,256,256,256,256,256,256,1024,1024,1024,1024};
    int c = 0;
    for (int i = 0; i < 12; i++) {
        r12.src[i] = (const float4*)srcs[i];
        r12.dst[i] = (float4*)dsts[i];
        r12.cum[i] = c;
        c += blks[i];
    }
    r12.cum[12] = c;   // 6144
    round_all<<<c, 256>>>(r12);

    const dim3 gD(DD / 128, MM / 128);
    const dim3 gF(DFF / 128, MM / 128);
    const dim3 gQKV(DD / 128, MM / 128, 3);
    const dim3 gKV2(DD / 128, MM / 128, 2);
    const dim3 gLog(SS / 128, SS / 128, BB * HH);
    const dim3 gAV(SS / 256, BB * HH);
    const int nSmBlocks = BB * HH * SS / 8;   // 8192

    // ---- fork: K2/V2 projections on side stream (depend only on encr) ----
    cudaEventRecord(evFork, 0);
    cudaStreamWaitEvent(s1, evFork, 0);
    {
        QKV qk;
        qk.A[0] = encr_p; qk.A[1] = encr_p; qk.A[2] = encr_p;
        qk.W[0] = t_k2; qk.W[1] = t_v2; qk.W[2] = t_v2;
        qk.b[0] = wk2b; qk.b[1] = wv2b; qk.b[2] = wv2b;
        qk.C[0] = k2_p; qk.C[1] = v2_p; qk.C[2] = v2_p;
        qk.round_flag[0] = 1; qk.round_flag[1] = 1; qk.round_flag[2] = 1;
        gemm_qkv<<<gKV2, 128, GEMM_SMEM_BYTES, s1>>>(qk);
    }
    cudaEventRecord(evKV2, s1);

    // ---- MHA1 (self-attention) on main stream ----
    {
        QKV qk;
        qk.A[0] = xr_p; qk.A[1] = xr_p; qk.A[2] = xr_p;
        qk.W[0] = t_q1; qk.W[1] = t_k1; qk.W[2] = t_v1;
        qk.b[0] = wq1b; qk.b[1] = wk1b; qk.b[2] = wv1b;
        qk.C[0] = q_p;  qk.C[1] = k_p;  qk.C[2] = v_p;
        qk.round_flag[0] = 1; qk.round_flag[1] = 1; qk.round_flag[2] = 1;
        gemm_qkv<<<gQKV, 128, GEMM_SMEM_BYTES>>>(qk);
    }
    attn_logits3<<<gLog, 128, LOG_SMEM_BYTES>>>(q_p, k_p, sub, aw1);
    softmax_rows_w<<<nSmBlocks, 256>>>(aw1);
    attn_av2<<<gAV, 128, AV_SMEM_BYTES>>>(aw1, v_p, ctx_p);
    gemm_ca<false><<<gD, 128, GEMM_SMEM_BYTES>>>(ctx_p, t_o1, wo1b, mha_p, DD, DD, 0);
    add_ln<<<MM, 256>>>(mha_p, x, ln1g, ln1b, res1_p, res1r_p);

    // ---- MHA2 (cross-attention) ----
    gemm_ca<false><<<gD, 128, GEMM_SMEM_BYTES>>>(res1r_p, t_q2, wq2b, q_p, DD, DD, 1);
    cudaStreamWaitEvent(0, evKV2, 0);   // join: k2/v2 ready
    attn_logits3<<<gLog, 128, LOG_SMEM_BYTES>>>(q_p, k2_p, pad, aw2);
    softmax_rows_w<<<nSmBlocks, 256>>>(aw2);
    attn_av2<<<gAV, 128, AV_SMEM_BYTES>>>(aw2, v2_p, ctx_p);
    gemm_ca<false><<<gD, 128, GEMM_SMEM_BYTES>>>(ctx_p, t_o2, wo2b, mha_p, DD, DD, 0);
    add_ln<<<MM, 256>>>(mha_p, res1_p, ln2g, ln2b, res2_p, res2r_p);

    // ---- FFN ----
    gemm_ca<true ><<<gF, 128, GEMM_SMEM_BYTES>>>(res2r_p, t_f1, f1b, ffn_p, DFF, DD, 1);
    gemm_ca<false><<<gD, 128, GEMM_SMEM_BYTES>>>(ffn_p, t_f2, f2b, mha_p, DD, DFF, 0);
    add_ln<<<MM, 256>>>(mha_p, res2_p, ln3g, ln3b, out3, nullptr);
}

// round 17
// speedup vs baseline: 1.4074x; 1.3704x over previous
#include <cuda_runtime.h>
#include <cuda_fp16.h>
#include <cstdint>
#include <math.h>

// Problem constants
#define BB   4
#define SS   1024
#define DD   1024
#define HH   16
#define DH   64
#define DFF  4096
#define MM   (BB*SS)          // 4096 rows
#define LN_EPS 1e-5f

// -------------------- scratch (static device globals; no runtime alloc) ----
__device__ __align__(16) __half h_wt[16u*1024u*1024u];   // transposed half weights
__device__ __align__(16) __half h_x[MM*DD];
__device__ __align__(16) __half h_enc[MM*DD];
__device__ __align__(16) __half h_q[MM*DD];
__device__ __align__(16) __half h_k[MM*DD];
__device__ __align__(16) __half h_v[MM*DD];
__device__ __align__(16) __half h_k2[MM*DD];
__device__ __align__(16) __half h_v2[MM*DD];
__device__ __align__(16) __half h_ctx[MM*DD];
__device__ __align__(16) __half h_res1[MM*DD];
__device__ __align__(16) __half h_res2[MM*DD];
__device__ __align__(16) __half h_ffn[(size_t)MM*DFF];
__device__ __align__(16) __half h_aw[(size_t)BB*HH*SS*SS];  // half attn weights (reused)
__device__ float  g_mha[MM*DD];
__device__ float  g_res1[MM*DD];
__device__ float  g_res2[MM*DD];

__device__ __forceinline__ uint32_t smem_u32(const void* p) {
    uint32_t a;
    asm("{ .reg .u64 t; cvta.to.shared.u64 t, %1; cvt.u32.u64 %0, t; }"
        : "=r"(a) : "l"(p));
    return a;
}
__device__ __forceinline__ void cp16(uint32_t dst, const void* src) {
    asm volatile("cp.async.ca.shared.global [%0], [%1], 16;" :: "r"(dst), "l"(src));
}
#define CP_COMMIT() asm volatile("cp.async.commit_group;")
#define CP_WAIT0()  asm volatile("cp.async.wait_group 0;")

__device__ __forceinline__ void mma_f16(float* c,
    uint32_t a0, uint32_t a1, uint32_t a2, uint32_t a3,
    uint32_t b0, uint32_t b1)
{
    asm volatile(
        "mma.sync.aligned.m16n8k16.row.col.f32.f16.f16.f32 "
        "{%0,%1,%2,%3}, {%4,%5,%6,%7}, {%8,%9}, {%0,%1,%2,%3};"
        : "+f"(c[0]), "+f"(c[1]), "+f"(c[2]), "+f"(c[3])
        : "r"(a0), "r"(a1), "r"(a2), "r"(a3), "r"(b0), "r"(b1));
}

// ============================================================================
// Prep 1: transpose-convert weights: in[K][N] fp32 -> out[N][K] half.
// ============================================================================
struct TW {
    const float* src[10];
    __half* dst[10];
    int K[10], N[10];
    int cum[11];   // cumulative 32x32 tile counts
};

__global__ __launch_bounds__(256) void transpose_w(TW w)
{
    __shared__ float tile[32][33];
    const int bid = blockIdx.x;
    int ti = 0;
#pragma unroll
    for (int i = 0; i < 10; i++)
        if (bid >= w.cum[i + 1]) ti = i + 1;
    const float* src = w.src[ti];
    __half* dst = w.dst[ti];
    const int K = w.K[ti], N = w.N[ti];
    const int lin = bid - w.cum[ti];
    const int tn = lin % (N >> 5), tk = lin / (N >> 5);
    const int n0 = tn * 32, k0 = tk * 32;
    const int tx = threadIdx.x & 31, ty = threadIdx.x >> 5;   // 32 x 8
#pragma unroll
    for (int j = 0; j < 32; j += 8)
        tile[ty + j][tx] = src[(size_t)(k0 + ty + j) * N + n0 + tx];
    __syncthreads();
#pragma unroll
    for (int j = 0; j < 32; j += 8)
        dst[(size_t)(n0 + ty + j) * K + k0 + tx] = __float2half_rn(tile[tx][ty + j]);
}

// Prep 2: straight fp32 -> half convert (4 floats per thread).
__global__ __launch_bounds__(256) void conv_h(
    const float4* __restrict__ in, __half* __restrict__ out)
{
    const int i = blockIdx.x * 256 + threadIdx.x;
    float4 v = in[i];
    __half2* o = (__half2*)(out + (size_t)i * 4);
    o[0] = __floats2half2_rn(v.x, v.y);
    o[1] = __floats2half2_rn(v.z, v.w);
}

// ============================================================================
// fp16 GEMM body: C = A@W + bias (A [M][K] half, Wt [N][K] half).
// CTA 128x128, BK=32 (2 k16 steps), 128 thr = 4 warps of 64x64.
// 2-stage cp.async pipeline. SMEM 40KB.
// ============================================================================
#define GAH 40                               // SMEM stride (halves)
#define G_TILE_H (128*GAH)                   // halves per tile
#define G_BUF_H (2*G_TILE_H)                 // A+B halves
#define GEMM_SMEM_BYTES (2*G_BUF_H*2)        // 40960

template<bool RELU, bool HALFOUT>
__device__ __forceinline__ void gemm_h_body(
    const __half* __restrict__ A, const __half* __restrict__ W,
    const float* __restrict__ bias, void* __restrict__ C,
    int N, int K, __half* sm, int row0, int col0)
{
    const uint32_t smb = smem_u32(sm);
    const int tid = threadIdx.x;
    const int wid = tid >> 5, lane = tid & 31;
    const int g = lane >> 2, t = lane & 3;
    const int wm = (wid >> 1) * 64;
    const int wn = (wid & 1) * 64;

    int l_r[4], l_c[4];
#pragma unroll
    for (int it = 0; it < 4; it++) {
        int lin = it * 128 + tid;
        l_r[it] = lin >> 2;           // 0..127
        l_c[it] = (lin & 3) * 8;      // half offset 0,8,16,24
    }

    float acc[4][8][4];
#pragma unroll
    for (int mt = 0; mt < 4; mt++)
#pragma unroll
        for (int nt = 0; nt < 8; nt++)
#pragma unroll
            for (int i = 0; i < 4; i++) acc[mt][nt][i] = 0.f;

    const int nchunk = K >> 5;

    {
        const uint32_t ab = smb, bb = smb + G_TILE_H * 2;
#pragma unroll
        for (int it = 0; it < 4; it++) {
            cp16(ab + (l_r[it] * GAH + l_c[it]) * 2,
                 A + (size_t)(row0 + l_r[it]) * K + l_c[it]);
            cp16(bb + (l_r[it] * GAH + l_c[it]) * 2,
                 W + (size_t)(col0 + l_r[it]) * K + l_c[it]);
        }
        CP_COMMIT();
    }

    for (int ic = 0; ic < nchunk; ic++) {
        const int p = ic & 1;
        CP_WAIT0();
        __syncthreads();
        if (ic + 1 < nchunk) {
            const int k1 = (ic + 1) << 5;
            const uint32_t ab = smb + (p ? 0 : G_BUF_H * 2);
            const uint32_t bb = ab + G_TILE_H * 2;
#pragma unroll
            for (int it = 0; it < 4; it++) {
                cp16(ab + (l_r[it] * GAH + l_c[it]) * 2,
                     A + (size_t)(row0 + l_r[it]) * K + k1 + l_c[it]);
                cp16(bb + (l_r[it] * GAH + l_c[it]) * 2,
                     W + (size_t)(col0 + l_r[it]) * K + k1 + l_c[it]);
            }
            CP_COMMIT();
        }

        const __half* sA = sm + (p ? G_BUF_H : 0);
        const __half* sB = sA + G_TILE_H;
#pragma unroll
        for (int ks = 0; ks < 2; ks++) {
            const int kh = ks * 16;
            uint32_t af[4][4];
#pragma unroll
            for (int mt = 0; mt < 4; mt++) {
                const int r = wm + mt * 16 + g;
                af[mt][0] = *(const uint32_t*)&sA[r * GAH + kh + 2 * t];
                af[mt][1] = *(const uint32_t*)&sA[(r + 8) * GAH + kh + 2 * t];
                af[mt][2] = *(const uint32_t*)&sA[r * GAH + kh + 2 * t + 8];
                af[mt][3] = *(const uint32_t*)&sA[(r + 8) * GAH + kh + 2 * t + 8];
            }
            uint32_t bf[8][2];
#pragma unroll
            for (int nt = 0; nt < 8; nt++) {
                const int n = wn + nt * 8 + g;
                bf[nt][0] = *(const uint32_t*)&sB[n * GAH + kh + 2 * t];
                bf[nt][1] = *(const uint32_t*)&sB[n * GAH + kh + 2 * t + 8];
            }
#pragma unroll
            for (int mt = 0; mt < 4; mt++)
#pragma unroll
                for (int nt = 0; nt < 8; nt++)
                    mma_f16(acc[mt][nt], af[mt][0], af[mt][1], af[mt][2], af[mt][3],
                            bf[nt][0], bf[nt][1]);
        }
    }

#pragma unroll
    for (int mt = 0; mt < 4; mt++) {
        const int ra = row0 + wm + mt * 16 + g;
#pragma unroll
        for (int nt = 0; nt < 8; nt++) {
            const int cc = col0 + wn + nt * 8 + 2 * t;
            float2 bv = *(const float2*)(bias + cc);
            float v0 = acc[mt][nt][0] + bv.x;
            float v1 = acc[mt][nt][1] + bv.y;
            float v2 = acc[mt][nt][2] + bv.x;
            float v3 = acc[mt][nt][3] + bv.y;
            if (RELU) {
                v0 = fmaxf(v0, 0.f); v1 = fmaxf(v1, 0.f);
                v2 = fmaxf(v2, 0.f); v3 = fmaxf(v3, 0.f);
            }
            if (HALFOUT) {
                __half* Ch = (__half*)C;
                *(__half2*)(Ch + (size_t)ra * N + cc) = __floats2half2_rn(v0, v1);
                *(__half2*)(Ch + (size_t)(ra + 8) * N + cc) = __floats2half2_rn(v2, v3);
            } else {
                float* Cf = (float*)C;
                *(float2*)(Cf + (size_t)ra * N + cc) = make_float2(v0, v1);
                *(float2*)(Cf + (size_t)(ra + 8) * N + cc) = make_float2(v2, v3);
            }
        }
    }
}

template<bool RELU, bool HALFOUT>
__global__ void __launch_bounds__(128, 2) gemm_h(
    const __half* __restrict__ A, const __half* __restrict__ W,
    const float* __restrict__ bias, void* __restrict__ C,
    int N, int K)
{
    extern __shared__ __half smh[];
    gemm_h_body<RELU, HALFOUT>(A, W, bias, C, N, K, smh,
                               blockIdx.y * 128, blockIdx.x * 128);
}

// Batched projections: z selects (A, W, bias, C). All half-out.
struct QKV {
    const __half* A[3];
    const __half* W[3];
    const float* b[3];
    __half* C[3];
};

__global__ void __launch_bounds__(128, 2) gemm_qkv(QKV q)
{
    extern __shared__ __half smh[];
    const int z = blockIdx.z;
    gemm_h_body<false, true>(q.A[z], q.W[z], q.b[z], q.C[z], DD, DD,
                             smh, blockIdx.y * 128, blockIdx.x * 128);
}

// ============================================================================
// Attention logits (fp16 one-shot): out = QK^T/8 + mask (fp32 out).
// Q [row][64] half, K [col][64] half, both k-contiguous. CTA 128x128 per bh.
// 128 thr = 4 warps of 64x64. SMEM 36KB -> 3 CTAs/SM.
// ============================================================================
#define LH 72
#define L_TILE_H (128*LH)
#define LOG_SMEM_BYTES (2*L_TILE_H*2)     // 36864

__global__ void __launch_bounds__(128, 3) attn_logits_h(
    const __half* __restrict__ q, const __half* __restrict__ k,
    const float* __restrict__ mask, float* __restrict__ out)
{
    extern __shared__ __half smh[];
    __half* Qs = smh;
    __half* Ks = smh + L_TILE_H;
    const uint32_t qs_u32 = smem_u32(Qs);
    const uint32_t ks_u32 = smem_u32(Ks);

    const int tid = threadIdx.x;
    const int wid = tid >> 5, lane = tid & 31;
    const int g = lane >> 2, t = lane & 3;
    const int wm = (wid >> 1) * 64;
    const int wn = (wid & 1) * 64;

    const int bh = blockIdx.z;
    const int b = bh >> 4, h = bh & 15;
    const int row0 = blockIdx.y * 128, col0 = blockIdx.x * 128;
    const __half* qb = q + (size_t)b * SS * DD + h * DH;
    const __half* kb = k + (size_t)b * SS * DD + h * DH;

#pragma unroll
    for (int it = 0; it < 8; it++) {
        const int lin = it * 128 + tid;
        const int r = lin >> 3, c = (lin & 7) * 8;
        cp16(qs_u32 + (r * LH + c) * 2, qb + (size_t)(row0 + r) * DD + c);
        cp16(ks_u32 + (r * LH + c) * 2, kb + (size_t)(col0 + r) * DD + c);
    }
    CP_COMMIT();
    CP_WAIT0();
    __syncthreads();

    float acc[4][8][4];
#pragma unroll
    for (int mt = 0; mt < 4; mt++)
#pragma unroll
        for (int nt = 0; nt < 8; nt++)
#pragma unroll
            for (int i = 0; i < 4; i++) acc[mt][nt][i] = 0.f;

#pragma unroll
    for (int ks = 0; ks < 4; ks++) {
        const int kh = ks * 16;
        uint32_t af[4][4];
#pragma unroll
        for (int mt = 0; mt < 4; mt++) {
            const int r = wm + mt * 16 + g;
            af[mt][0] = *(const uint32_t*)&Qs[r * LH + kh + 2 * t];
            af[mt][1] = *(const uint32_t*)&Qs[(r + 8) * LH + kh + 2 * t];
            af[mt][2] = *(const uint32_t*)&Qs[r * LH + kh + 2 * t + 8];
            af[mt][3] = *(const uint32_t*)&Qs[(r + 8) * LH + kh + 2 * t + 8];
        }
        uint32_t bf[8][2];
#pragma unroll
        for (int nt = 0; nt < 8; nt++) {
            const int n = wn + nt * 8 + g;
            bf[nt][0] = *(const uint32_t*)&Ks[n * LH + kh + 2 * t];
            bf[nt][1] = *(const uint32_t*)&Ks[n * LH + kh + 2 * t + 8];
        }
#pragma unroll
        for (int mt = 0; mt < 4; mt++)
#pragma unroll
            for (int nt = 0; nt < 8; nt++)
                mma_f16(acc[mt][nt], af[mt][0], af[mt][1], af[mt][2], af[mt][3],
                        bf[nt][0], bf[nt][1]);
    }

    const float* mb = mask + (size_t)b * SS * SS;
    float* ob = out + (size_t)bh * SS * SS;
#pragma unroll
    for (int mt = 0; mt < 4; mt++) {
        const int r = row0 + wm + mt * 16 + g;
#pragma unroll
        for (int nt = 0; nt < 8; nt++) {
            const int c = col0 + wn + nt * 8 + 2 * t;
            float2 m0 = *(const float2*)(mb + (size_t)r * SS + c);
            float2 m1 = *(const float2*)(mb + (size_t)(r + 8) * SS + c);
            *(float2*)(ob + (size_t)r * SS + c) =
                make_float2(acc[mt][nt][0] * 0.125f + m0.x,
                            acc[mt][nt][1] * 0.125f + m0.y);
            *(float2*)(ob + (size_t)(r + 8) * SS + c) =
                make_float2(acc[mt][nt][2] * 0.125f + m1.x,
                            acc[mt][nt][3] * 0.125f + m1.y);
        }
    }
}

// ============================================================================
// Batched AV (fp16): ctx = aw_h @ V_h. CTA 256x64, 128 thr = 4 warps 64x64.
// A [row][k] half (k-contig); V [k][n] half (n-contig) -> B frags via u16 pairs.
// ============================================================================
#define AVAH 40
#define AVBH 72
#define AVA_TILE_H (256*AVAH)             // 10240
#define AVB_TILE_H (32*AVBH)              // 2304
#define AV_BUF_H (AVA_TILE_H + AVB_TILE_H)
#define AV_SMEM_BYTES (2*AV_BUF_H*2)      // 50176

__global__ void __launch_bounds__(128, 2) attn_av_h(
    const __half* __restrict__ w, const __half* __restrict__ v,
    __half* __restrict__ ctx)
{
    extern __shared__ __half smh[];
    const uint32_t smb = smem_u32(smh);
    const int tid = threadIdx.x;
    const int wid = tid >> 5, lane = tid & 31;
    const int g = lane >> 2, t = lane & 3;
    const int wm = wid * 64;

    const int bh = blockIdx.y;
    const int b = bh >> 4, h = bh & 15;
    const int row0 = blockIdx.x * 256;
    const __half* wb = w + (size_t)bh * SS * SS;
    const __half* vb = v + (size_t)b * SS * DD + h * DH;

    int a_r[8], a_c[8], b_k[2], b_n[2];
#pragma unroll
    for (int it = 0; it < 8; it++) {
        int lin = it * 128 + tid;
        a_r[it] = lin >> 2;               // 0..255
        a_c[it] = (lin & 3) * 8;          // 0,8,16,24 halves
    }
#pragma unroll
    for (int it = 0; it < 2; it++) {
        int lin = it * 128 + tid;
        b_k[it] = lin >> 3;               // 0..31
        b_n[it] = (lin & 7) * 8;          // 0..56 halves
    }

    float acc[4][8][4];
#pragma unroll
    for (int mt = 0; mt < 4; mt++)
#pragma unroll
        for (int nt = 0; nt < 8; nt++)
#pragma unroll
            for (int i = 0; i < 4; i++) acc[mt][nt][i] = 0.f;

    {
        const uint32_t ab = smb, bb = smb + AVA_TILE_H * 2;
#pragma unroll
        for (int it = 0; it < 8; it++)
            cp16(ab + (a_r[it] * AVAH + a_c[it]) * 2,
                 wb + (size_t)(row0 + a_r[it]) * SS + a_c[it]);
#pragma unroll
        for (int it = 0; it < 2; it++)
            cp16(bb + (b_k[it] * AVBH + b_n[it]) * 2,
                 vb + (size_t)b_k[it] * DD + b_n[it]);
        CP_COMMIT();
    }

    for (int ic = 0; ic < 32; ic++) {
        const int p = ic & 1;
        CP_WAIT0();
        __syncthreads();
        if (ic + 1 < 32) {
            const int k1 = (ic + 1) << 5;
            const uint32_t ab = smb + (p ? 0 : AV_BUF_H * 2);
            const uint32_t bb = ab + AVA_TILE_H * 2;
#pragma unroll
            for (int it = 0; it < 8; it++)
                cp16(ab + (a_r[it] * AVAH + a_c[it]) * 2,
                     wb + (size_t)(row0 + a_r[it]) * SS + k1 + a_c[it]);
#pragma unroll
            for (int it = 0; it < 2; it++)
                cp16(bb + (b_k[it] * AVBH + b_n[it]) * 2,
                     vb + (size_t)(k1 + b_k[it]) * DD + b_n[it]);
            CP_COMMIT();
        }

        const __half* sA = smh + (p ? AV_BUF_H : 0);
        const unsigned short* sBu =
            (const unsigned short*)(sA + AVA_TILE_H);
#pragma unroll
        for (int ks = 0; ks < 2; ks++) {
            const int kh = ks * 16;
            uint32_t af[4][4];
#pragma unroll
            for (int mt = 0; mt < 4; mt++) {
                const int r = wm + mt * 16 + g;
                af[mt][0] = *(const uint32_t*)&sA[r * AVAH + kh + 2 * t];
                af[mt][1] = *(const uint32_t*)&sA[(r + 8) * AVAH + kh + 2 * t];
                af[mt][2] = *(const uint32_t*)&sA[r * AVAH + kh + 2 * t + 8];
                af[mt][3] = *(const uint32_t*)&sA[(r + 8) * AVAH + kh + 2 * t + 8];
            }
            uint32_t bf[8][2];
#pragma unroll
            for (int nt = 0; nt < 8; nt++) {
                const int n = nt * 8 + g;
                uint32_t lo0 = sBu[(kh + 2 * t) * AVBH + n];
                uint32_t hi0 = sBu[(kh + 2 * t + 1) * AVBH + n];
                uint32_t lo1 = sBu[(kh + 2 * t + 8) * AVBH + n];
                uint32_t hi1 = sBu[(kh + 2 * t + 9) * AVBH + n];
                bf[nt][0] = lo0 | (hi0 << 16);
                bf[nt][1] = lo1 | (hi1 << 16);
            }
#pragma unroll
            for (int mt = 0; mt < 4; mt++)
#pragma unroll
                for (int nt = 0; nt < 8; nt++)
                    mma_f16(acc[mt][nt], af[mt][0], af[mt][1], af[mt][2], af[mt][3],
                            bf[nt][0], bf[nt][1]);
        }
    }

#pragma unroll
    for (int mt = 0; mt < 4; mt++) {
        const int ra = row0 + wm + mt * 16 + g;
#pragma unroll
        for (int nt = 0; nt < 8; nt++) {
            const int cc = nt * 8 + 2 * t;
            __half* d0 = ctx + (size_t)(b * SS + ra) * DD + h * DH + cc;
            __half* d1 = ctx + (size_t)(b * SS + ra + 8) * DD + h * DH + cc;
            *(__half2*)d0 = __floats2half2_rn(acc[mt][nt][0], acc[mt][nt][1]);
            *(__half2*)d1 = __floats2half2_rn(acc[mt][nt][2], acc[mt][nt][3]);
        }
    }
}

// ============================================================================
// Softmax: warp-per-row; writes fp32 normalized weights (d_out) + half copy.
// ============================================================================
__global__ __launch_bounds__(256) void softmax_rows_h(
    float* __restrict__ w, __half* __restrict__ wh)
{
    const int row = blockIdx.x * 8 + (threadIdx.x >> 5);
    const int lane = threadIdx.x & 31;
    float* p = w + (size_t)row * SS;
    __half* ph = wh + (size_t)row * SS;

    float4 v[8];
#pragma unroll
    for (int j = 0; j < 8; j++)
        v[j] = *(const float4*)(p + lane * 4 + j * 128);

    float m = -1e30f;
#pragma unroll
    for (int j = 0; j < 8; j++)
        m = fmaxf(m, fmaxf(fmaxf(v[j].x, v[j].y), fmaxf(v[j].z, v[j].w)));
#pragma unroll
    for (int o = 16; o; o >>= 1) m = fmaxf(m, __shfl_xor_sync(0xffffffffu, m, o));

    float s = 0.f;
#pragma unroll
    for (int j = 0; j < 8; j++) {
        v[j].x = __expf(v[j].x - m); v[j].y = __expf(v[j].y - m);
        v[j].z = __expf(v[j].z - m); v[j].w = __expf(v[j].w - m);
        s += (v[j].x + v[j].y) + (v[j].z + v[j].w);
    }
#pragma unroll
    for (int o = 16; o; o >>= 1) s += __shfl_xor_sync(0xffffffffu, s, o);
    const float inv = 1.f / s;

#pragma unroll
    for (int j = 0; j < 8; j++) {
        float4 o4;
        o4.x = v[j].x * inv; o4.y = v[j].y * inv;
        o4.z = v[j].z * inv; o4.w = v[j].w * inv;
        *(float4*)(p + lane * 4 + j * 128) = o4;
        __half2* hp = (__half2*)(ph + lane * 4 + j * 128);
        hp[0] = __floats2half2_rn(o4.x, o4.y);
        hp[1] = __floats2half2_rn(o4.z, o4.w);
    }
}

// ============================================================================
// Fused residual add + LayerNorm; fp32 out + optional half twin.
// ============================================================================
__global__ __launch_bounds__(256) void add_ln(
    const float* __restrict__ a, const float* __restrict__ r,
    const float* __restrict__ g, const float* __restrict__ beta,
    float* __restrict__ out, __half* __restrict__ outh)
{
    const size_t base = (size_t)blockIdx.x * DD;
    const int tid = threadIdx.x;
    float4 va = *(const float4*)(a + base + tid * 4);
    float4 vr = *(const float4*)(r + base + tid * 4);
    float x0 = va.x + vr.x, x1 = va.y + vr.y, x2 = va.z + vr.z, x3 = va.w + vr.w;

    float s = x0 + x1 + x2 + x3;
    float sq = x0 * x0 + x1 * x1 + x2 * x2 + x3 * x3;
#pragma unroll
    for (int o = 16; o; o >>= 1) {
        s  += __shfl_xor_sync(0xffffffffu, s, o);
        sq += __shfl_xor_sync(0xffffffffu, sq, o);
    }
    __shared__ float ss[8], ssq[8];
    if ((tid & 31) == 0) { ss[tid >> 5] = s; ssq[tid >> 5] = sq; }
    __syncthreads();
    float ts = 0.f, tsq = 0.f;
#pragma unroll
    for (int i = 0; i < 8; i++) { ts += ss[i]; tsq += ssq[i]; }
    const float mu = ts * (1.0f / DD);
    const float var = tsq * (1.0f / DD) - mu * mu;
    const float rs = rsqrtf(var + LN_EPS);

    float4 gg = *(const float4*)(g + tid * 4);
    float4 bb = *(const float4*)(beta + tid * 4);
    float4 o4;
    o4.x = (x0 - mu) * rs * gg.x + bb.x;
    o4.y = (x1 - mu) * rs * gg.y + bb.y;
    o4.z = (x2 - mu) * rs * gg.z + bb.z;
    o4.w = (x3 - mu) * rs * gg.w + bb.w;
    *(float4*)(out + base + tid * 4) = o4;
    if (outh) {
        __half2* hp = (__half2*)(outh + base + tid * 4);
        hp[0] = __floats2half2_rn(o4.x, o4.y);
        hp[1] = __floats2half2_rn(o4.z, o4.w);
    }
}

// ============================================================================
// Host launch
// ============================================================================
extern "C" void kernel_launch(void* const* d_in, const int* in_sizes, int n_in,
                              void* d_out, int out_size)
{
    (void)in_sizes; (void)n_in; (void)out_size;
    const float* x    = (const float*)d_in[0];
    const float* enc  = (const float*)d_in[1];
    const float* pad  = (const float*)d_in[2];
    const float* sub  = (const float*)d_in[3];
    const float* wq1w = (const float*)d_in[4];   const float* wq1b = (const float*)d_in[5];
    const float* wk1w = (const float*)d_in[6];   const float* wk1b = (const float*)d_in[7];
    const float* wv1w = (const float*)d_in[8];   const float* wv1b = (const float*)d_in[9];
    const float* wo1w = (const float*)d_in[10];  const float* wo1b = (const float*)d_in[11];
    const float* wq2w = (const float*)d_in[12];  const float* wq2b = (const float*)d_in[13];
    const float* wk2w = (const float*)d_in[14];  const float* wk2b = (const float*)d_in[15];
    const float* wv2w = (const float*)d_in[16];  const float* wv2b = (const float*)d_in[17];
    const float* wo2w = (const float*)d_in[18];  const float* wo2b = (const float*)d_in[19];
    const float* f1w  = (const float*)d_in[20];  const float* f1b  = (const float*)d_in[21];
    const float* f2w  = (const float*)d_in[22];  const float* f2b  = (const float*)d_in[23];
    const float* ln1g = (const float*)d_in[24];  const float* ln1b = (const float*)d_in[25];
    const float* ln2g = (const float*)d_in[26];  const float* ln2b = (const float*)d_in[27];
    const float* ln3g = (const float*)d_in[28];  const float* ln3b = (const float*)d_in[29];

    static __half *hw_p, *hx_p, *henc_p, *hq_p, *hk_p, *hv_p, *hk2_p, *hv2_p;
    static __half *hctx_p, *hres1_p, *hres2_p, *hffn_p, *haw_p;
    static float *mha_p, *res1_p, *res2_p;
    static cudaStream_t s1;
    static cudaEvent_t evFork, evKV2;
    static bool init = false;
    if (!init) {
        cudaGetSymbolAddress((void**)&hw_p, h_wt);
        cudaGetSymbolAddress((void**)&hx_p, h_x);
        cudaGetSymbolAddress((void**)&henc_p, h_enc);
        cudaGetSymbolAddress((void**)&hq_p, h_q);
        cudaGetSymbolAddress((void**)&hk_p, h_k);
        cudaGetSymbolAddress((void**)&hv_p, h_v);
        cudaGetSymbolAddress((void**)&hk2_p, h_k2);
        cudaGetSymbolAddress((void**)&hv2_p, h_v2);
        cudaGetSymbolAddress((void**)&hctx_p, h_ctx);
        cudaGetSymbolAddress((void**)&hres1_p, h_res1);
        cudaGetSymbolAddress((void**)&hres2_p, h_res2);
        cudaGetSymbolAddress((void**)&hffn_p, h_ffn);
        cudaGetSymbolAddress((void**)&haw_p, h_aw);
        cudaGetSymbolAddress((void**)&mha_p, g_mha);
        cudaGetSymbolAddress((void**)&res1_p, g_res1);
        cudaGetSymbolAddress((void**)&res2_p, g_res2);
        cudaStreamCreateWithFlags(&s1, cudaStreamNonBlocking);
        cudaEventCreateWithFlags(&evFork, cudaEventDisableTiming);
        cudaEventCreateWithFlags(&evKV2, cudaEventDisableTiming);
        cudaFuncSetAttribute((const void*)gemm_h<false,false>,
            cudaFuncAttributeMaxDynamicSharedMemorySize, GEMM_SMEM_BYTES);
        cudaFuncSetAttribute((const void*)gemm_h<false,true>,
            cudaFuncAttributeMaxDynamicSharedMemorySize, GEMM_SMEM_BYTES);
        cudaFuncSetAttribute((const void*)gemm_h<true,true>,
            cudaFuncAttributeMaxDynamicSharedMemorySize, GEMM_SMEM_BYTES);
        cudaFuncSetAttribute((const void*)gemm_qkv,
            cudaFuncAttributeMaxDynamicSharedMemorySize, GEMM_SMEM_BYTES);
        cudaFuncSetAttribute((const void*)attn_logits_h,
            cudaFuncAttributeMaxDynamicSharedMemorySize, LOG_SMEM_BYTES);
        cudaFuncSetAttribute((const void*)attn_av_h,
            cudaFuncAttributeMaxDynamicSharedMemorySize, AV_SMEM_BYTES);
        init = true;
    }

    // transposed half weight slots
    const size_t M1 = 1024u * 1024u;
    __half* t_q1 = hw_p + 0*M1;  __half* t_k1 = hw_p + 1*M1;
    __half* t_v1 = hw_p + 2*M1;  __half* t_o1 = hw_p + 3*M1;
    __half* t_q2 = hw_p + 4*M1;  __half* t_k2 = hw_p + 5*M1;
    __half* t_v2 = hw_p + 6*M1;  __half* t_o2 = hw_p + 7*M1;
    __half* t_f1 = hw_p + 8*M1;   // [4096][1024]
    __half* t_f2 = hw_p + 12*M1;  // [1024][4096]

    // Output layout: out3 | attn_w1 | attn_w2
    float* out3 = (float*)d_out;
    float* aw1  = out3 + (size_t)MM * DD;
    float* aw2  = aw1 + (size_t)BB * HH * SS * SS;
    // half attn-weight buffer is REUSED for both MHAs (never live together)
    __half* awh = haw_p;

    // ---- prep: transpose-convert weights; convert x/enc ----
    TW tw;
    const float* wsrc[10] = {wq1w, wk1w, wv1w, wo1w, wq2w, wk2w, wv2w, wo2w, f1w, f2w};
    __half* wdst[10] = {t_q1, t_k1, t_v1, t_o1, t_q2, t_k2, t_v2, t_o2, t_f1, t_f2};
    int wK[10] = {DD,DD,DD,DD,DD,DD,DD,DD,DD,DFF};
    int wN[10] = {DD,DD,DD,DD,DD,DD,DD,DD,DFF,DD};
    int c = 0;
    for (int i = 0; i < 10; i++) {
        tw.src[i] = wsrc[i]; tw.dst[i] = wdst[i];
        tw.K[i] = wK[i]; tw.N[i] = wN[i];
        tw.cum[i] = c;
        c += (wK[i] >> 5) * (wN[i] >> 5);
    }
    tw.cum[10] = c;   // 16384
    transpose_w<<<c, 256>>>(tw);
    conv_h<<<MM*DD/1024, 256>>>((const float4*)x, hx_p);
    conv_h<<<MM*DD/1024, 256>>>((const float4*)enc, henc_p);

    const dim3 gD(DD / 128, MM / 128);
    const dim3 gF(DFF / 128, MM / 128);
    const dim3 gQKV(DD / 128, MM / 128, 3);
    const dim3 gKV2(DD / 128, MM / 128, 2);
    const dim3 gLog(SS / 128, SS / 128, BB * HH);
    const dim3 gAV(SS / 256, BB * HH);
    const int nSmBlocks = BB * HH * SS / 8;   // 8192

    // ---- fork: K2/V2 projections on side stream ----
    cudaEventRecord(evFork, 0);
    cudaStreamWaitEvent(s1, evFork, 0);
    {
        QKV qk;
        qk.A[0] = henc_p; qk.A[1] = henc_p; qk.A[2] = henc_p;
        qk.W[0] = t_k2; qk.W[1] = t_v2; qk.W[2] = t_v2;
        qk.b[0] = wk2b; qk.b[1] = wv2b; qk.b[2] = wv2b;
        qk.C[0] = hk2_p; qk.C[1] = hv2_p; qk.C[2] = hv2_p;
        gemm_qkv<<<gKV2, 128, GEMM_SMEM_BYTES, s1>>>(qk);
    }
    cudaEventRecord(evKV2, s1);

    // ---- MHA1 (self-attention) ----
    {
        QKV qk;
        qk.A[0] = hx_p; qk.A[1] = hx_p; qk.A[2] = hx_p;
        qk.W[0] = t_q1; qk.W[1] = t_k1; qk.W[2] = t_v1;
        qk.b[0] = wq1b; qk.b[1] = wk1b; qk.b[2] = wv1b;
        qk.C[0] = hq_p; qk.C[1] = hk_p; qk.C[2] = hv_p;
        gemm_qkv<<<gQKV, 128, GEMM_SMEM_BYTES>>>(qk);
    }
    attn_logits_h<<<gLog, 128, LOG_SMEM_BYTES>>>(hq_p, hk_p, sub, aw1);
    softmax_rows_h<<<nSmBlocks, 256>>>(aw1, awh);
    attn_av_h<<<gAV, 128, AV_SMEM_BYTES>>>(awh, hv_p, hctx_p);
    gemm_h<false,false><<<gD, 128, GEMM_SMEM_BYTES>>>(hctx_p, t_o1, wo1b, mha_p, DD, DD);
    add_ln<<<MM, 256>>>(mha_p, x, ln1g, ln1b, res1_p, hres1_p);

    // ---- MHA2 (cross-attention) ----
    gemm_h<false,true><<<gD, 128, GEMM_SMEM_BYTES>>>(hres1_p, t_q2, wq2b, hq_p, DD, DD);
    cudaStreamWaitEvent(0, evKV2, 0);
    attn_logits_h<<<gLog, 128, LOG_SMEM_BYTES>>>(hq_p, hk2_p, pad, aw2);
    softmax_rows_h<<<nSmBlocks, 256>>>(aw2, awh);
    attn_av_h<<<gAV, 128, AV_SMEM_BYTES>>>(awh, hv2_p, hctx_p);
    gemm_h<false,false><<<gD, 128, GEMM_SMEM_BYTES>>>(hctx_p, t_o2, wo2b, mha_p, DD, DD);
    add_ln<<<MM, 256>>>(mha_p, res1_p, ln2g, ln2b, res2_p, hres2_p);

    // ---- FFN ----
    gemm_h<true,true><<<gF, 128, GEMM_SMEM_BYTES>>>(hres2_p, t_f1, f1b, hffn_p, DFF, DD);
    gemm_h<false,false><<<gD, 128, GEMM_SMEM_BYTES>>>(hffn_p, t_f2, f2b, mha_p, DD, DFF);
    add_ln<<<MM, 256>>>(mha_p, res2_p, ln3g, ln3b, out3, nullptr);
}